// round 12
// baseline (speedup 1.0000x reference)
#include <cuda_runtime.h>
#include <cuda_bf16.h>
#include <cstdint>

// ---------------- problem constants ----------------
#define N_NODES 50000
#define N_EDGES 250000
#define M_PAD 50048           // 391 * 128
// dims: 300 -> 1024 -> 512 -> 256 -> 128 -> 2048

// ---------------- static device scratch ----------------
// __device__ globals load zeroed; g_ideg/g_odeg are re-zeroed inside the
// layer-1 gather_pre (after their last use) so every graph replay starts
// from zero.
__device__ __align__(256) float g_t[(size_t)N_NODES * 512];             // GEMM fp32 out (layers 2-4)
__device__ __align__(256) float g_y[(size_t)N_NODES * 128];             // layer-4 activation fp32
__device__ __align__(256) __nv_bfloat16 g_Ah0[(size_t)M_PAD * 1024];    // split A ping
__device__ __align__(256) __nv_bfloat16 g_Al0[(size_t)M_PAD * 1024];
__device__ __align__(256) __nv_bfloat16 g_Ah1[(size_t)M_PAD * 1024];    // split A pong
__device__ __align__(256) __nv_bfloat16 g_Al1[(size_t)M_PAD * 1024];
__device__ __align__(256) __nv_bfloat16 g_Wh[1277952];                  // all layers, hi plane
__device__ __align__(256) __nv_bfloat16 g_Wl[1277952];                  // all layers, lo plane
__device__ __align__(256) float g_dinv_out[N_NODES];
__device__ __align__(256) float g_dinv_in[N_NODES];
// CSC structures
__device__ __align__(256) int g_ideg[N_NODES];   // zero at entry
__device__ __align__(256) int g_odeg[N_NODES];   // zero at entry
__device__ __align__(256) int g_off[N_NODES + 4];
__device__ __align__(256) int g_cur[N_NODES];
__device__ __align__(256) int g_csc[N_EDGES];
__device__ __align__(256) int g_bsum[128];

// per-layer W plane offsets (bf16 elements)
#define WOFF0 0
#define WOFF1 327680
#define WOFF2 851968
#define WOFF3 983040
#define WOFF4 1015808

// ================= helpers =================
__device__ __forceinline__ uint32_t smem_u32(const void* p) {
    uint32_t a;
    asm("{ .reg .u64 t; cvta.to.shared.u64 t, %1; cvt.u32.u64 %0, t; }" : "=r"(a) : "l"(p));
    return a;
}

__device__ __forceinline__ void ldm_x4(uint32_t& r0, uint32_t& r1, uint32_t& r2, uint32_t& r3,
                                       uint32_t addr) {
    asm volatile("ldmatrix.sync.aligned.m8n8.x4.shared.b16 {%0,%1,%2,%3}, [%4];"
                 : "=r"(r0), "=r"(r1), "=r"(r2), "=r"(r3) : "r"(addr));
}

__device__ __forceinline__ void mma_bf16(float* d, const uint32_t* a, const uint32_t* b) {
    asm volatile("mma.sync.aligned.m16n8k16.row.col.f32.bf16.bf16.f32 "
                 "{%0,%1,%2,%3}, {%4,%5,%6,%7}, {%8,%9}, {%0,%1,%2,%3};"
                 : "+f"(d[0]), "+f"(d[1]), "+f"(d[2]), "+f"(d[3])
                 : "r"(a[0]), "r"(a[1]), "r"(a[2]), "r"(a[3]), "r"(b[0]), "r"(b[1]));
}

// fp32 -> bf16 hi/lo split, packed pair (low 16 bits = even-k element)
__device__ __forceinline__ void split2(float a, float b, uint32_t& hi, uint32_t& lo) {
    __nv_bfloat16 ah = __float2bfloat16(a);
    __nv_bfloat16 bh = __float2bfloat16(b);
    __nv_bfloat16 al = __float2bfloat16(a - __bfloat162float(ah));
    __nv_bfloat16 bl = __float2bfloat16(b - __bfloat162float(bh));
    hi = ((uint32_t)__bfloat16_as_ushort(bh) << 16) | (uint32_t)__bfloat16_as_ushort(ah);
    lo = ((uint32_t)__bfloat16_as_ushort(bl) << 16) | (uint32_t)__bfloat16_as_ushort(al);
}

// ================= pipelined bf16x3 mma.sync GEMM (128x128, 2-stage) =================
// C = A @ Wt^T, A = Ah+Al [M_PAD, sA], Wt = Wh+Wl [N, sA] (k-major rows).
// Epilogue modes:
//  0: C[m][n] = d                         (fp32 t for gather_post)
//  1: A'(next) = split(leaky(d + bias[n]) * dout[m])   (stride sNext)
//  2: C[m][n] = d + bias[n]               (final output)
#define APAD 40                 // bf16 row stride in smem (80B)
#define TILE_B 10240            // 128*40*2 bytes per tile
#define STAGE_B 40960           // 4 tiles
#define SMEM_TOTAL_B 81920      // 2 stages

__global__ __launch_bounds__(256)
void gemm_mma(const __nv_bfloat16* __restrict__ Ah, const __nv_bfloat16* __restrict__ Al,
              const __nv_bfloat16* __restrict__ Wh, const __nv_bfloat16* __restrict__ Wl,
              float* __restrict__ C, int M, int N, int sA,
              int mode, const float* __restrict__ bias, const float* __restrict__ dout,
              __nv_bfloat16* __restrict__ oAh, __nv_bfloat16* __restrict__ oAl, int sNext) {
    extern __shared__ __nv_bfloat16 dsm[];
    const uint32_t sbase = smem_u32(dsm);

    const int tid = threadIdx.x, lane = tid & 31, wid = tid >> 5;
    const int bm = blockIdx.y * 128, bn = blockIdx.x * 128;
    const int wm = (wid >> 1) * 32, wn = (wid & 1) * 64;
    const int nkt = sA >> 5;

    const int g = lane >> 3, l8 = lane & 7;
    const uint32_t aoff = (uint32_t)(((g & 1) * 8 + l8) * APAD + (g >> 1) * 8);
    const uint32_t boff = (uint32_t)(((g >> 1) * 8 + l8) * APAD + (g & 1) * 8);

    auto load_stage = [&](int kt, int st) {
        const int k0 = kt << 5;
        #pragma unroll
        for (int it = 0; it < 8; it++) {
            const int idx = it * 256 + tid;
            const int t = idx >> 9, rc = idx & 511;
            const int r = rc >> 2, c = rc & 3;
            const __nv_bfloat16* gsrc;
            if (t == 0)      gsrc = Ah + (size_t)(bm + r) * sA + k0 + c * 8;
            else if (t == 1) gsrc = Al + (size_t)(bm + r) * sA + k0 + c * 8;
            else if (t == 2) gsrc = Wh + (size_t)(bn + r) * sA + k0 + c * 8;
            else             gsrc = Wl + (size_t)(bn + r) * sA + k0 + c * 8;
            const uint32_t d = sbase + st * STAGE_B + t * TILE_B + r * 80 + c * 16;
            asm volatile("cp.async.cg.shared.global [%0], [%1], 16;" :: "r"(d), "l"(gsrc));
        }
    };

    float acc[2][8][4] = {};

    load_stage(0, 0);
    asm volatile("cp.async.commit_group;" ::: "memory");

    for (int kt = 0; kt < nkt; kt++) {
        const int st = kt & 1;
        if (kt + 1 < nkt) {
            load_stage(kt + 1, st ^ 1);
            asm volatile("cp.async.commit_group;" ::: "memory");
            asm volatile("cp.async.wait_group 1;" ::: "memory");
        } else {
            asm volatile("cp.async.wait_group 0;" ::: "memory");
        }
        __syncthreads();

        const uint32_t sAh_u = sbase + st * STAGE_B;
        const uint32_t sAl_u = sAh_u + TILE_B;
        const uint32_t sBh_u = sAh_u + 2 * TILE_B;
        const uint32_t sBl_u = sAh_u + 3 * TILE_B;

        #pragma unroll
        for (int ks = 0; ks < 2; ks++) {
            uint32_t ah[2][4], al[2][4];
            #pragma unroll
            for (int mb = 0; mb < 2; mb++) {
                const uint32_t off = (aoff + (uint32_t)(wm + mb * 16) * APAD + ks * 16) * 2;
                ldm_x4(ah[mb][0], ah[mb][1], ah[mb][2], ah[mb][3], sAh_u + off);
                ldm_x4(al[mb][0], al[mb][1], al[mb][2], al[mb][3], sAl_u + off);
            }
            #pragma unroll
            for (int nbp = 0; nbp < 4; nbp++) {
                const uint32_t off = (boff + (uint32_t)(wn + nbp * 16) * APAD + ks * 16) * 2;
                uint32_t bh[4], bl[4];
                ldm_x4(bh[0], bh[1], bh[2], bh[3], sBh_u + off);
                ldm_x4(bl[0], bl[1], bl[2], bl[3], sBl_u + off);
                #pragma unroll
                for (int h = 0; h < 2; h++) {
                    #pragma unroll
                    for (int mb = 0; mb < 2; mb++) {
                        float* d = acc[mb][nbp * 2 + h];
                        mma_bf16(d, ah[mb], bh + h * 2);
                        mma_bf16(d, ah[mb], bl + h * 2);
                        mma_bf16(d, al[mb], bh + h * 2);
                    }
                }
            }
        }
        __syncthreads();
    }

    const int mrow = lane >> 2, ncol = (lane & 3) * 2;
    #pragma unroll
    for (int mb = 0; mb < 2; mb++) {
        const int m0 = bm + wm + mb * 16 + mrow;
        float dv0 = 0.f, dv1 = 0.f;
        if (mode == 1) {
            if (m0 < M) dv0 = dout[m0];
            if (m0 + 8 < M) dv1 = dout[m0 + 8];
        }
        #pragma unroll
        for (int nb = 0; nb < 8; nb++) {
            const float* d = acc[mb][nb];
            const int n = bn + wn + nb * 8 + ncol;
            if (mode == 0) {
                if (m0 < M)
                    *reinterpret_cast<float2*>(C + (size_t)m0 * N + n) = make_float2(d[0], d[1]);
                if (m0 + 8 < M)
                    *reinterpret_cast<float2*>(C + (size_t)(m0 + 8) * N + n) = make_float2(d[2], d[3]);
            } else if (mode == 2) {
                const float b0 = bias[n], b1 = bias[n + 1];
                if (m0 < M)
                    *reinterpret_cast<float2*>(C + (size_t)m0 * N + n) = make_float2(d[0] + b0, d[1] + b1);
                if (m0 + 8 < M)
                    *reinterpret_cast<float2*>(C + (size_t)(m0 + 8) * N + n) = make_float2(d[2] + b0, d[3] + b1);
            } else {
                const float b0 = bias[n], b1 = bias[n + 1];
                if (m0 < M) {
                    float v0 = d[0] + b0, v1 = d[1] + b1;
                    v0 = ((v0 < 0.f) ? 0.01f * v0 : v0) * dv0;
                    v1 = ((v1 < 0.f) ? 0.01f * v1 : v1) * dv0;
                    uint32_t hi, lo; split2(v0, v1, hi, lo);
                    *reinterpret_cast<uint32_t*>(oAh + (size_t)m0 * sNext + n) = hi;
                    *reinterpret_cast<uint32_t*>(oAl + (size_t)m0 * sNext + n) = lo;
                }
                if (m0 + 8 < M) {
                    float v0 = d[2] + b0, v1 = d[3] + b1;
                    v0 = ((v0 < 0.f) ? 0.01f * v0 : v0) * dv1;
                    v1 = ((v1 < 0.f) ? 0.01f * v1 : v1) * dv1;
                    uint32_t hi, lo; split2(v0, v1, hi, lo);
                    *reinterpret_cast<uint32_t*>(oAh + (size_t)(m0 + 8) * sNext + n) = hi;
                    *reinterpret_cast<uint32_t*>(oAl + (size_t)(m0 + 8) * sNext + n) = lo;
                }
            }
        }
    }
}

// ================= fused W prep: all 5 layers in one launch =================
__global__ void prep_w_all(const float* __restrict__ W0, const float* __restrict__ W1,
                           const float* __restrict__ W2, const float* __restrict__ W3,
                           const float* __restrict__ W4,
                           __nv_bfloat16* __restrict__ Wh, __nv_bfloat16* __restrict__ Wl) {
    const int starts[6] = {0, 163840, 425984, 491520, 507904, 638976};
    const int Ks[5]     = {300, 1024, 512, 256, 128};
    const int Ns[5]     = {1024, 512, 256, 128, 2048};
    const int Kpads[5]  = {320, 1024, 512, 256, 128};
    const int woffs[5]  = {WOFF0, WOFF1, WOFF2, WOFF3, WOFF4};
    const float* Ws[5]  = {W0, W1, W2, W3, W4};

    int idx = blockIdx.x * blockDim.x + threadIdx.x;
    int stride = gridDim.x * blockDim.x;
    for (; idx < 638976; idx += stride) {
        int l = 0;
        #pragma unroll
        for (int q = 1; q < 5; q++) if (idx >= starts[q]) l = q;
        const int p = idx - starts[l];
        const int Kp2 = Kpads[l] >> 1;
        const int n = p / Kp2, pk = p - n * Kp2;
        const int k = pk * 2;
        const int K = Ks[l], N = Ns[l];
        float w0 = 0.f, w1 = 0.f;
        if (k < K)     w0 = Ws[l][(size_t)k * N + n];
        if (k + 1 < K) w1 = Ws[l][(size_t)(k + 1) * N + n];
        uint32_t hi, lo; split2(w0, w1, hi, lo);
        ((uint32_t*)(Wh + woffs[l]))[p] = hi;
        ((uint32_t*)(Wl + woffs[l]))[p] = lo;
    }
}

// ================= CSC build (parallel scan) =================
__global__ void hist_kernel(const int* __restrict__ src, const int* __restrict__ dst,
                            int* __restrict__ odeg, int* __restrict__ ideg, int nE) {
    int e = blockIdx.x * blockDim.x + threadIdx.x;
    if (e >= nE) return;
    int s = src[e], d = dst[e];
    if ((unsigned)s < N_NODES) atomicAdd(&odeg[s], 1);
    if ((unsigned)d < N_NODES) atomicAdd(&ideg[d], 1);
}

#define SCAN_BS 512
#define SCAN_NB ((N_NODES + SCAN_BS - 1) / SCAN_BS)  // 98

__global__ void blocksum_kernel(const int* __restrict__ deg, int* __restrict__ bsum) {
    __shared__ int sh[SCAN_BS];
    int i = blockIdx.x * SCAN_BS + threadIdx.x;
    sh[threadIdx.x] = (i < N_NODES) ? deg[i] : 0;
    __syncthreads();
    for (int s = SCAN_BS / 2; s > 0; s >>= 1) {
        if (threadIdx.x < s) sh[threadIdx.x] += sh[threadIdx.x + s];
        __syncthreads();
    }
    if (threadIdx.x == 0) bsum[blockIdx.x] = sh[0];
}

__global__ void scanpart_kernel(int* __restrict__ bsum, int nb) {
    __shared__ int sh[256];
    int t = threadIdx.x;
    int v = (t < nb) ? bsum[t] : 0;
    sh[t] = v;
    __syncthreads();
    for (int s = 1; s < 256; s <<= 1) {
        int add = (t >= s) ? sh[t - s] : 0;
        __syncthreads();
        sh[t] += add;
        __syncthreads();
    }
    if (t < nb) bsum[t] = sh[t] - v;  // exclusive
}

__global__ void offsets_dinv_kernel(const int* __restrict__ ideg, const int* __restrict__ odeg,
                                    const int* __restrict__ bsum,
                                    int* __restrict__ off, int* __restrict__ cur,
                                    float* __restrict__ dout, float* __restrict__ din) {
    __shared__ int sh[SCAN_BS];
    int t = threadIdx.x;
    int i = blockIdx.x * SCAN_BS + t;
    int v = (i < N_NODES) ? ideg[i] : 0;
    if (i < N_NODES) {
        dout[i] = rsqrtf(fmaxf((float)odeg[i], 1.0f));
        din[i]  = rsqrtf(fmaxf((float)v, 1.0f));
    }
    sh[t] = v;
    __syncthreads();
    for (int s = 1; s < SCAN_BS; s <<= 1) {
        int add = (t >= s) ? sh[t - s] : 0;
        __syncthreads();
        sh[t] += add;
        __syncthreads();
    }
    if (i < N_NODES) {
        int excl = sh[t] - v + bsum[blockIdx.x];
        off[i] = excl;
        cur[i] = excl;
        if (i == N_NODES - 1) off[N_NODES] = excl + v;
    }
}

__global__ void fill_kernel(const int* __restrict__ src, const int* __restrict__ dst,
                            int* __restrict__ cur, int* __restrict__ csc, int nE) {
    int e = blockIdx.x * blockDim.x + threadIdx.x;
    if (e >= nE) return;
    int s = src[e], d = dst[e];
    if ((unsigned)s >= N_NODES || (unsigned)d >= N_NODES) return;
    int pos = atomicAdd(&cur[d], 1);
    csc[pos] = s;
}

// ================= gather_pre: u = dinv_in ⊙ S (opt dout ⊙) y  -> split bf16 =================
// Inner edge loop unrolled x4 for MLP (gather is latency-bound per ncu R9).
// cleanup != 0: also re-zero ideg/odeg[node] for the next graph replay (their
// last use is offsets_dinv_kernel, which already ran).
__global__ __launch_bounds__(256)
void gather_pre(const float* __restrict__ y, const float* __restrict__ dout,
                const int* __restrict__ off, const int* __restrict__ csc,
                int K4, int Kpad4,
                __nv_bfloat16* __restrict__ Ah, __nv_bfloat16* __restrict__ Al, int sNext,
                const float* __restrict__ dinv_in,
                int* __restrict__ cl_ideg, int* __restrict__ cl_odeg) {
    const int node = blockIdx.x * 8 + (threadIdx.x >> 5);
    if (node >= N_NODES) return;
    const int lane = threadIdx.x & 31;
    if (cl_ideg && lane == 0) { cl_ideg[node] = 0; cl_odeg[node] = 0; }
    const int beg = off[node], end = off[node + 1];
    const float di = dinv_in[node];
    const float4* y4 = (const float4*)y;

    for (int c = lane; c < Kpad4; c += 32) {
        float4 acc = make_float4(0.f, 0.f, 0.f, 0.f);
        if (c < K4) {
            int j = beg;
            for (; j + 3 < end; j += 4) {
                const int s0 = csc[j], s1 = csc[j + 1], s2 = csc[j + 2], s3 = csc[j + 3];
                float4 v0 = y4[(size_t)s0 * K4 + c];
                float4 v1 = y4[(size_t)s1 * K4 + c];
                float4 v2 = y4[(size_t)s2 * K4 + c];
                float4 v3 = y4[(size_t)s3 * K4 + c];
                float c0 = 1.f, c1 = 1.f, c2 = 1.f, c3 = 1.f;
                if (dout) { c0 = dout[s0]; c1 = dout[s1]; c2 = dout[s2]; c3 = dout[s3]; }
                acc.x += v0.x * c0 + v1.x * c1 + v2.x * c2 + v3.x * c3;
                acc.y += v0.y * c0 + v1.y * c1 + v2.y * c2 + v3.y * c3;
                acc.z += v0.z * c0 + v1.z * c1 + v2.z * c2 + v3.z * c3;
                acc.w += v0.w * c0 + v1.w * c1 + v2.w * c2 + v3.w * c3;
            }
            for (; j < end; j++) {
                const int s = csc[j];
                float4 v = y4[(size_t)s * K4 + c];
                const float sc = dout ? dout[s] : 1.0f;
                acc.x += v.x * sc; acc.y += v.y * sc; acc.z += v.z * sc; acc.w += v.w * sc;
            }
        }
        uint32_t h0, l0, h1, l1;
        split2(acc.x * di, acc.y * di, h0, l0);
        split2(acc.z * di, acc.w * di, h1, l1);
        const size_t eo = (size_t)node * sNext + c * 4;
        *reinterpret_cast<uint2*>(Ah + eo) = make_uint2(h0, h1);
        *reinterpret_cast<uint2*>(Al + eo) = make_uint2(l0, l1);
    }
}

// ================= gather_post (edge loop unrolled x4) =================
__global__ __launch_bounds__(256)
void gather_post(const float* __restrict__ t, const int* __restrict__ off,
                 const int* __restrict__ csc, int N4, int cpn,
                 __nv_bfloat16* __restrict__ Ah, __nv_bfloat16* __restrict__ Al, int sNext,
                 const float* __restrict__ bias, const float* __restrict__ dinv_in,
                 const float* __restrict__ dinv_out, float* __restrict__ outF) {
    const int gw = blockIdx.x * 8 + (threadIdx.x >> 5);
    const int lane = threadIdx.x & 31;
    const int node = gw / cpn, chunk = gw - node * cpn;
    if (node >= N_NODES) return;
    const int c = chunk * 32 + lane;

    const float4* t4 = (const float4*)t;
    const int beg = off[node], end = off[node + 1];
    float4 acc = make_float4(0.f, 0.f, 0.f, 0.f);
    int j = beg;
    for (; j + 3 < end; j += 4) {
        const int s0 = csc[j], s1 = csc[j + 1], s2 = csc[j + 2], s3 = csc[j + 3];
        float4 v0 = t4[(size_t)s0 * N4 + c];
        float4 v1 = t4[(size_t)s1 * N4 + c];
        float4 v2 = t4[(size_t)s2 * N4 + c];
        float4 v3 = t4[(size_t)s3 * N4 + c];
        acc.x += v0.x + v1.x + v2.x + v3.x;
        acc.y += v0.y + v1.y + v2.y + v3.y;
        acc.z += v0.z + v1.z + v2.z + v3.z;
        acc.w += v0.w + v1.w + v2.w + v3.w;
    }
    for (; j < end; j++) {
        const int s = csc[j];
        float4 v = t4[(size_t)s * N4 + c];
        acc.x += v.x; acc.y += v.y; acc.z += v.z; acc.w += v.w;
    }
    const float di = dinv_in[node];
    const float dv = dinv_out[node];
    const float4 b = ((const float4*)bias)[c];
    float v0 = fmaf(acc.x, di, b.x);
    float v1 = fmaf(acc.y, di, b.y);
    float v2 = fmaf(acc.z, di, b.z);
    float v3 = fmaf(acc.w, di, b.w);
    v0 = ((v0 < 0.f) ? 0.01f * v0 : v0) * dv;
    v1 = ((v1 < 0.f) ? 0.01f * v1 : v1) * dv;
    v2 = ((v2 < 0.f) ? 0.01f * v2 : v2) * dv;
    v3 = ((v3 < 0.f) ? 0.01f * v3 : v3) * dv;

    if (outF) {
        ((float4*)outF)[(size_t)node * N4 + c] = make_float4(v0, v1, v2, v3);
    } else {
        uint32_t h0, l0, h1, l1;
        split2(v0, v1, h0, l0);
        split2(v2, v3, h1, l1);
        const size_t eo = (size_t)node * sNext + c * 4;
        *reinterpret_cast<uint2*>(Ah + eo) = make_uint2(h0, h1);
        *reinterpret_cast<uint2*>(Al + eo) = make_uint2(l0, l1);
    }
}

// ================= launch =================
extern "C" void kernel_launch(void* const* d_in, const int* in_sizes, int n_in,
                              void* d_out, int out_size) {
    const float* x = (const float*)d_in[0];
    const int* ei = (const int*)d_in[1];   // int32 (JAX x64 disabled)
    const float* W[5] = {(const float*)d_in[2], (const float*)d_in[4], (const float*)d_in[6],
                         (const float*)d_in[8], (const float*)d_in[10]};
    const float* B[5] = {(const float*)d_in[3], (const float*)d_in[5], (const float*)d_in[7],
                         (const float*)d_in[9], (const float*)d_in[11]};

    const int M = N_NODES;
    const int nE = N_EDGES;
    const int* src = ei;
    const int* dstp = ei + nE;

    float *tP, *yP, *doutP, *dinP;
    __nv_bfloat16 *Ah0, *Al0, *Ah1, *Al1, *WhP, *WlP;
    int *idegP, *odegP, *offP, *curP, *cscP, *bsumP;
    cudaGetSymbolAddress((void**)&tP, g_t);
    cudaGetSymbolAddress((void**)&yP, g_y);
    cudaGetSymbolAddress((void**)&Ah0, g_Ah0);
    cudaGetSymbolAddress((void**)&Al0, g_Al0);
    cudaGetSymbolAddress((void**)&Ah1, g_Ah1);
    cudaGetSymbolAddress((void**)&Al1, g_Al1);
    cudaGetSymbolAddress((void**)&WhP, g_Wh);
    cudaGetSymbolAddress((void**)&WlP, g_Wl);
    cudaGetSymbolAddress((void**)&doutP, g_dinv_out);
    cudaGetSymbolAddress((void**)&dinP, g_dinv_in);
    cudaGetSymbolAddress((void**)&idegP, g_ideg);
    cudaGetSymbolAddress((void**)&odegP, g_odeg);
    cudaGetSymbolAddress((void**)&offP, g_off);
    cudaGetSymbolAddress((void**)&curP, g_cur);
    cudaGetSymbolAddress((void**)&cscP, g_csc);
    cudaGetSymbolAddress((void**)&bsumP, g_bsum);

    cudaFuncSetAttribute(gemm_mma, cudaFuncAttributeMaxDynamicSharedMemorySize, SMEM_TOTAL_B);

    // degrees + parallel scan + CSC fill
    hist_kernel<<<(nE + 255) / 256, 256>>>(src, dstp, odegP, idegP, nE);
    blocksum_kernel<<<SCAN_NB, SCAN_BS>>>(idegP, bsumP);
    scanpart_kernel<<<1, 256>>>(bsumP, SCAN_NB);
    offsets_dinv_kernel<<<SCAN_NB, SCAN_BS>>>(idegP, odegP, bsumP, offP, curP, doutP, dinP);
    fill_kernel<<<(nE + 255) / 256, 256>>>(src, dstp, curP, cscP, nE);
    // layer-1 pre-aggregation (K=300 -> split A0, stride 320); also re-zeroes
    // ideg/odeg for the next replay (their last use was offsets_dinv_kernel)
    gather_pre<<<(M + 7) / 8, 256>>>(x, doutP, offP, cscP, 75, 80, Ah0, Al0, 320, dinP,
                                     idegP, odegP);
    // all weight planes
    prep_w_all<<<640, 256>>>(W[0], W[1], W[2], W[3], W[4], WhP, WlP);

    // Layer 1 GEMM (K=320, N=1024) epilogue -> split A1
    {
        dim3 grid(1024 / 128, M_PAD / 128);
        gemm_mma<<<grid, 256, SMEM_TOTAL_B>>>(Ah0, Al0, WhP + WOFF0, WlP + WOFF0, nullptr,
                                              M, 1024, 320, 1, B[0], doutP, Ah1, Al1, 1024);
    }
    // Layer 2 (K=1024, N=512)
    {
        dim3 grid(512 / 128, M_PAD / 128);
        gemm_mma<<<grid, 256, SMEM_TOTAL_B>>>(Ah1, Al1, WhP + WOFF1, WlP + WOFF1, tP,
                                              M, 512, 1024, 0, nullptr, nullptr, nullptr, nullptr, 0);
    }
    gather_post<<<(M * 4 + 7) / 8, 256>>>(tP, offP, cscP, 128, 4, Ah0, Al0, 512,
                                          B[1], dinP, doutP, nullptr);
    // Layer 3 (K=512, N=256)
    {
        dim3 grid(256 / 128, M_PAD / 128);
        gemm_mma<<<grid, 256, SMEM_TOTAL_B>>>(Ah0, Al0, WhP + WOFF2, WlP + WOFF2, tP,
                                              M, 256, 512, 0, nullptr, nullptr, nullptr, nullptr, 0);
    }
    gather_post<<<(M * 2 + 7) / 8, 256>>>(tP, offP, cscP, 64, 2, Ah1, Al1, 256,
                                          B[2], dinP, doutP, nullptr);
    // Layer 4 (K=256, N=128) -> fp32 y
    {
        dim3 grid(128 / 128, M_PAD / 128);
        gemm_mma<<<grid, 256, SMEM_TOTAL_B>>>(Ah1, Al1, WhP + WOFF3, WlP + WOFF3, tP,
                                              M, 128, 256, 0, nullptr, nullptr, nullptr, nullptr, 0);
    }
    gather_post<<<(M + 7) / 8, 256>>>(tP, offP, cscP, 32, 1, nullptr, nullptr, 0,
                                      B[3], dinP, doutP, yP);
    // Layer 5 (aggregate-first, K=128, N=2048) -> d_out
    gather_pre<<<(M + 7) / 8, 256>>>(yP, nullptr, offP, cscP, 32, 32, Ah0, Al0, 128, dinP,
                                     nullptr, nullptr);
    {
        dim3 grid(2048 / 128, M_PAD / 128);
        gemm_mma<<<grid, 256, SMEM_TOTAL_B>>>(Ah0, Al0, WhP + WOFF4, WlP + WOFF4, (float*)d_out,
                                              M, 2048, 128, 2, B[4], nullptr, nullptr, nullptr, 0);
    }
}

// round 13
// speedup vs baseline: 1.0987x; 1.0987x over previous
#include <cuda_runtime.h>
#include <cuda_bf16.h>
#include <cstdint>

// ---------------- problem constants ----------------
#define N_NODES 50000
#define N_EDGES 250000
#define M_PAD 50048           // 391 * 128
// dims: 300 -> 1024 -> 512 -> 256 -> 128 -> 2048

// ---------------- static device scratch ----------------
// __device__ globals load zeroed; g_ideg/g_odeg are re-zeroed at the END of
// each replay (cleanup_kernel) so every graph replay starts from zero.
__device__ __align__(256) float g_t[(size_t)N_NODES * 512];             // GEMM fp32 out (layers 2-4)
__device__ __align__(256) float g_y[(size_t)N_NODES * 128];             // layer-4 activation fp32
__device__ __align__(256) __nv_bfloat16 g_Ah0[(size_t)M_PAD * 1024];    // split A ping
__device__ __align__(256) __nv_bfloat16 g_Al0[(size_t)M_PAD * 1024];
__device__ __align__(256) __nv_bfloat16 g_Ah1[(size_t)M_PAD * 1024];    // split A pong
__device__ __align__(256) __nv_bfloat16 g_Al1[(size_t)M_PAD * 1024];
__device__ __align__(256) __nv_bfloat16 g_Wh[1277952];                  // all layers, hi plane
__device__ __align__(256) __nv_bfloat16 g_Wl[1277952];                  // all layers, lo plane
__device__ __align__(256) float g_dinv_out[N_NODES];
__device__ __align__(256) float g_dinv_in[N_NODES];
// CSC structures
__device__ __align__(256) int g_ideg[N_NODES];   // zero at entry
__device__ __align__(256) int g_odeg[N_NODES];   // zero at entry
__device__ __align__(256) int g_off[N_NODES + 4];
__device__ __align__(256) int g_cur[N_NODES];
__device__ __align__(256) int g_csc[N_EDGES];
__device__ __align__(256) int g_bsum[128];

// per-layer W plane offsets (bf16 elements)
#define WOFF0 0
#define WOFF1 327680
#define WOFF2 851968
#define WOFF3 983040
#define WOFF4 1015808

// ================= helpers =================
__device__ __forceinline__ uint32_t smem_u32(const void* p) {
    uint32_t a;
    asm("{ .reg .u64 t; cvta.to.shared.u64 t, %1; cvt.u32.u64 %0, t; }" : "=r"(a) : "l"(p));
    return a;
}

__device__ __forceinline__ void ldm_x4(uint32_t& r0, uint32_t& r1, uint32_t& r2, uint32_t& r3,
                                       uint32_t addr) {
    asm volatile("ldmatrix.sync.aligned.m8n8.x4.shared.b16 {%0,%1,%2,%3}, [%4];"
                 : "=r"(r0), "=r"(r1), "=r"(r2), "=r"(r3) : "r"(addr));
}

__device__ __forceinline__ void mma_bf16(float* d, const uint32_t* a, const uint32_t* b) {
    asm volatile("mma.sync.aligned.m16n8k16.row.col.f32.bf16.bf16.f32 "
                 "{%0,%1,%2,%3}, {%4,%5,%6,%7}, {%8,%9}, {%0,%1,%2,%3};"
                 : "+f"(d[0]), "+f"(d[1]), "+f"(d[2]), "+f"(d[3])
                 : "r"(a[0]), "r"(a[1]), "r"(a[2]), "r"(a[3]), "r"(b[0]), "r"(b[1]));
}

// fp32 -> bf16 hi/lo split, packed pair (low 16 bits = even-k element)
__device__ __forceinline__ void split2(float a, float b, uint32_t& hi, uint32_t& lo) {
    __nv_bfloat16 ah = __float2bfloat16(a);
    __nv_bfloat16 bh = __float2bfloat16(b);
    __nv_bfloat16 al = __float2bfloat16(a - __bfloat162float(ah));
    __nv_bfloat16 bl = __float2bfloat16(b - __bfloat162float(bh));
    hi = ((uint32_t)__bfloat16_as_ushort(bh) << 16) | (uint32_t)__bfloat16_as_ushort(ah);
    lo = ((uint32_t)__bfloat16_as_ushort(bl) << 16) | (uint32_t)__bfloat16_as_ushort(al);
}

// ================= pipelined bf16x3 mma.sync GEMM (128x128, 2-stage) =================
// Single __syncthreads per k-tile: the barrier that admits stage kt also
// proves all warps finished reading buffer (kt+1)&1 in iteration kt-1, so
// the prefetch issued after it is race-free.
// Epilogue modes:
//  0: C[m][n] = d                         (fp32 t for gather_post)
//  1: A'(next) = split(leaky(d + bias[n]) * dout[m])   (stride sNext)
//  2: C[m][n] = d + bias[n]               (final output)
#define APAD 40                 // bf16 row stride in smem (80B)
#define TILE_B 10240            // 128*40*2 bytes per tile
#define STAGE_B 40960           // 4 tiles
#define SMEM_TOTAL_B 81920      // 2 stages

__global__ __launch_bounds__(256)
void gemm_mma(const __nv_bfloat16* __restrict__ Ah, const __nv_bfloat16* __restrict__ Al,
              const __nv_bfloat16* __restrict__ Wh, const __nv_bfloat16* __restrict__ Wl,
              float* __restrict__ C, int M, int N, int sA,
              int mode, const float* __restrict__ bias, const float* __restrict__ dout,
              __nv_bfloat16* __restrict__ oAh, __nv_bfloat16* __restrict__ oAl, int sNext) {
    extern __shared__ __nv_bfloat16 dsm[];
    const uint32_t sbase = smem_u32(dsm);

    const int tid = threadIdx.x, lane = tid & 31, wid = tid >> 5;
    const int bm = blockIdx.y * 128, bn = blockIdx.x * 128;
    const int wm = (wid >> 1) * 32, wn = (wid & 1) * 64;
    const int nkt = sA >> 5;

    const int g = lane >> 3, l8 = lane & 7;
    const uint32_t aoff = (uint32_t)(((g & 1) * 8 + l8) * APAD + (g >> 1) * 8);
    const uint32_t boff = (uint32_t)(((g >> 1) * 8 + l8) * APAD + (g & 1) * 8);

    auto load_stage = [&](int kt, int st) {
        const int k0 = kt << 5;
        #pragma unroll
        for (int it = 0; it < 8; it++) {
            const int idx = it * 256 + tid;
            const int t = idx >> 9, rc = idx & 511;
            const int r = rc >> 2, c = rc & 3;
            const __nv_bfloat16* gsrc;
            if (t == 0)      gsrc = Ah + (size_t)(bm + r) * sA + k0 + c * 8;
            else if (t == 1) gsrc = Al + (size_t)(bm + r) * sA + k0 + c * 8;
            else if (t == 2) gsrc = Wh + (size_t)(bn + r) * sA + k0 + c * 8;
            else             gsrc = Wl + (size_t)(bn + r) * sA + k0 + c * 8;
            const uint32_t d = sbase + st * STAGE_B + t * TILE_B + r * 80 + c * 16;
            asm volatile("cp.async.ca.shared.global [%0], [%1], 16;" :: "r"(d), "l"(gsrc));
        }
    };

    float acc[2][8][4] = {};

    load_stage(0, 0);
    asm volatile("cp.async.commit_group;" ::: "memory");

    for (int kt = 0; kt < nkt; kt++) {
        const int st = kt & 1;

        asm volatile("cp.async.wait_group 0;" ::: "memory");   // stage kt arrived
        __syncthreads();                                        // + buf st^1 readers done

        if (kt + 1 < nkt) {
            load_stage(kt + 1, st ^ 1);
            asm volatile("cp.async.commit_group;" ::: "memory");
        }

        const uint32_t sAh_u = sbase + st * STAGE_B;
        const uint32_t sAl_u = sAh_u + TILE_B;
        const uint32_t sBh_u = sAh_u + 2 * TILE_B;
        const uint32_t sBl_u = sAh_u + 3 * TILE_B;

        #pragma unroll
        for (int ks = 0; ks < 2; ks++) {
            uint32_t ah[2][4], al[2][4];
            #pragma unroll
            for (int mb = 0; mb < 2; mb++) {
                const uint32_t off = (aoff + (uint32_t)(wm + mb * 16) * APAD + ks * 16) * 2;
                ldm_x4(ah[mb][0], ah[mb][1], ah[mb][2], ah[mb][3], sAh_u + off);
                ldm_x4(al[mb][0], al[mb][1], al[mb][2], al[mb][3], sAl_u + off);
            }
            #pragma unroll
            for (int nbp = 0; nbp < 4; nbp++) {
                const uint32_t off = (boff + (uint32_t)(wn + nbp * 16) * APAD + ks * 16) * 2;
                uint32_t bh[4], bl[4];
                ldm_x4(bh[0], bh[1], bh[2], bh[3], sBh_u + off);
                ldm_x4(bl[0], bl[1], bl[2], bl[3], sBl_u + off);
                #pragma unroll
                for (int h = 0; h < 2; h++) {
                    #pragma unroll
                    for (int mb = 0; mb < 2; mb++) {
                        float* d = acc[mb][nbp * 2 + h];
                        mma_bf16(d, ah[mb], bh + h * 2);
                        mma_bf16(d, ah[mb], bl + h * 2);
                        mma_bf16(d, al[mb], bh + h * 2);
                    }
                }
            }
        }
    }

    const int mrow = lane >> 2, ncol = (lane & 3) * 2;
    #pragma unroll
    for (int mb = 0; mb < 2; mb++) {
        const int m0 = bm + wm + mb * 16 + mrow;
        float dv0 = 0.f, dv1 = 0.f;
        if (mode == 1) {
            if (m0 < M) dv0 = dout[m0];
            if (m0 + 8 < M) dv1 = dout[m0 + 8];
        }
        #pragma unroll
        for (int nb = 0; nb < 8; nb++) {
            const float* d = acc[mb][nb];
            const int n = bn + wn + nb * 8 + ncol;
            if (mode == 0) {
                if (m0 < M)
                    *reinterpret_cast<float2*>(C + (size_t)m0 * N + n) = make_float2(d[0], d[1]);
                if (m0 + 8 < M)
                    *reinterpret_cast<float2*>(C + (size_t)(m0 + 8) * N + n) = make_float2(d[2], d[3]);
            } else if (mode == 2) {
                const float b0 = bias[n], b1 = bias[n + 1];
                if (m0 < M)
                    *reinterpret_cast<float2*>(C + (size_t)m0 * N + n) = make_float2(d[0] + b0, d[1] + b1);
                if (m0 + 8 < M)
                    *reinterpret_cast<float2*>(C + (size_t)(m0 + 8) * N + n) = make_float2(d[2] + b0, d[3] + b1);
            } else {
                const float b0 = bias[n], b1 = bias[n + 1];
                if (m0 < M) {
                    float v0 = d[0] + b0, v1 = d[1] + b1;
                    v0 = ((v0 < 0.f) ? 0.01f * v0 : v0) * dv0;
                    v1 = ((v1 < 0.f) ? 0.01f * v1 : v1) * dv0;
                    uint32_t hi, lo; split2(v0, v1, hi, lo);
                    *reinterpret_cast<uint32_t*>(oAh + (size_t)m0 * sNext + n) = hi;
                    *reinterpret_cast<uint32_t*>(oAl + (size_t)m0 * sNext + n) = lo;
                }
                if (m0 + 8 < M) {
                    float v0 = d[2] + b0, v1 = d[3] + b1;
                    v0 = ((v0 < 0.f) ? 0.01f * v0 : v0) * dv1;
                    v1 = ((v1 < 0.f) ? 0.01f * v1 : v1) * dv1;
                    uint32_t hi, lo; split2(v0, v1, hi, lo);
                    *reinterpret_cast<uint32_t*>(oAh + (size_t)(m0 + 8) * sNext + n) = hi;
                    *reinterpret_cast<uint32_t*>(oAl + (size_t)(m0 + 8) * sNext + n) = lo;
                }
            }
        }
    }
}

// ================= fused W prep: all 5 layers in one launch =================
__global__ void prep_w_all(const float* __restrict__ W0, const float* __restrict__ W1,
                           const float* __restrict__ W2, const float* __restrict__ W3,
                           const float* __restrict__ W4,
                           __nv_bfloat16* __restrict__ Wh, __nv_bfloat16* __restrict__ Wl) {
    const int starts[6] = {0, 163840, 425984, 491520, 507904, 638976};
    const int Ks[5]     = {300, 1024, 512, 256, 128};
    const int Ns[5]     = {1024, 512, 256, 128, 2048};
    const int Kpads[5]  = {320, 1024, 512, 256, 128};
    const int woffs[5]  = {WOFF0, WOFF1, WOFF2, WOFF3, WOFF4};
    const float* Ws[5]  = {W0, W1, W2, W3, W4};

    int idx = blockIdx.x * blockDim.x + threadIdx.x;
    int stride = gridDim.x * blockDim.x;
    for (; idx < 638976; idx += stride) {
        int l = 0;
        #pragma unroll
        for (int q = 1; q < 5; q++) if (idx >= starts[q]) l = q;
        const int p = idx - starts[l];
        const int Kp2 = Kpads[l] >> 1;
        const int n = p / Kp2, pk = p - n * Kp2;
        const int k = pk * 2;
        const int K = Ks[l], N = Ns[l];
        float w0 = 0.f, w1 = 0.f;
        if (k < K)     w0 = Ws[l][(size_t)k * N + n];
        if (k + 1 < K) w1 = Ws[l][(size_t)(k + 1) * N + n];
        uint32_t hi, lo; split2(w0, w1, hi, lo);
        ((uint32_t*)(Wh + woffs[l]))[p] = hi;
        ((uint32_t*)(Wl + woffs[l]))[p] = lo;
    }
}

// ================= CSC build (parallel scan) =================
__global__ void hist_kernel(const int* __restrict__ src, const int* __restrict__ dst,
                            int* __restrict__ odeg, int* __restrict__ ideg, int nE) {
    int e = blockIdx.x * blockDim.x + threadIdx.x;
    if (e >= nE) return;
    int s = src[e], d = dst[e];
    if ((unsigned)s < N_NODES) atomicAdd(&odeg[s], 1);
    if ((unsigned)d < N_NODES) atomicAdd(&ideg[d], 1);
}

#define SCAN_BS 512
#define SCAN_NB ((N_NODES + SCAN_BS - 1) / SCAN_BS)  // 98

__global__ void blocksum_kernel(const int* __restrict__ deg, int* __restrict__ bsum) {
    __shared__ int sh[SCAN_BS];
    int i = blockIdx.x * SCAN_BS + threadIdx.x;
    sh[threadIdx.x] = (i < N_NODES) ? deg[i] : 0;
    __syncthreads();
    for (int s = SCAN_BS / 2; s > 0; s >>= 1) {
        if (threadIdx.x < s) sh[threadIdx.x] += sh[threadIdx.x + s];
        __syncthreads();
    }
    if (threadIdx.x == 0) bsum[blockIdx.x] = sh[0];
}

__global__ void scanpart_kernel(int* __restrict__ bsum, int nb) {
    __shared__ int sh[256];
    int t = threadIdx.x;
    int v = (t < nb) ? bsum[t] : 0;
    sh[t] = v;
    __syncthreads();
    for (int s = 1; s < 256; s <<= 1) {
        int add = (t >= s) ? sh[t - s] : 0;
        __syncthreads();
        sh[t] += add;
        __syncthreads();
    }
    if (t < nb) bsum[t] = sh[t] - v;  // exclusive
}

__global__ void offsets_dinv_kernel(const int* __restrict__ ideg, const int* __restrict__ odeg,
                                    const int* __restrict__ bsum,
                                    int* __restrict__ off, int* __restrict__ cur,
                                    float* __restrict__ dout, float* __restrict__ din) {
    __shared__ int sh[SCAN_BS];
    int t = threadIdx.x;
    int i = blockIdx.x * SCAN_BS + t;
    int v = (i < N_NODES) ? ideg[i] : 0;
    if (i < N_NODES) {
        dout[i] = rsqrtf(fmaxf((float)odeg[i], 1.0f));
        din[i]  = rsqrtf(fmaxf((float)v, 1.0f));
    }
    sh[t] = v;
    __syncthreads();
    for (int s = 1; s < SCAN_BS; s <<= 1) {
        int add = (t >= s) ? sh[t - s] : 0;
        __syncthreads();
        sh[t] += add;
        __syncthreads();
    }
    if (i < N_NODES) {
        int excl = sh[t] - v + bsum[blockIdx.x];
        off[i] = excl;
        cur[i] = excl;
        if (i == N_NODES - 1) off[N_NODES] = excl + v;
    }
}

__global__ void fill_kernel(const int* __restrict__ src, const int* __restrict__ dst,
                            int* __restrict__ cur, int* __restrict__ csc, int nE) {
    int e = blockIdx.x * blockDim.x + threadIdx.x;
    if (e >= nE) return;
    int s = src[e], d = dst[e];
    if ((unsigned)s >= N_NODES || (unsigned)d >= N_NODES) return;
    int pos = atomicAdd(&cur[d], 1);
    csc[pos] = s;
}

__global__ void cleanup_kernel(int* __restrict__ ideg, int* __restrict__ odeg) {
    int i = blockIdx.x * blockDim.x + threadIdx.x;
    if (i < N_NODES) { ideg[i] = 0; odeg[i] = 0; }
}

// ================= gather_pre: u = dinv_in ⊙ S (opt dout ⊙) y  -> split bf16 =================
__global__ __launch_bounds__(256)
void gather_pre(const float* __restrict__ y, const float* __restrict__ dout,
                const int* __restrict__ off, const int* __restrict__ csc,
                int K4, int Kpad4,
                __nv_bfloat16* __restrict__ Ah, __nv_bfloat16* __restrict__ Al, int sNext,
                const float* __restrict__ dinv_in) {
    const int node = blockIdx.x * 8 + (threadIdx.x >> 5);
    if (node >= N_NODES) return;
    const int lane = threadIdx.x & 31;
    const int beg = off[node], end = off[node + 1];
    const float di = dinv_in[node];
    const float4* y4 = (const float4*)y;

    for (int c = lane; c < Kpad4; c += 32) {
        float4 acc = make_float4(0.f, 0.f, 0.f, 0.f);
        if (c < K4) {
            for (int j = beg; j < end; j++) {
                const int s = csc[j];
                float4 v = y4[(size_t)s * K4 + c];
                const float sc = dout ? dout[s] : 1.0f;
                acc.x += v.x * sc; acc.y += v.y * sc; acc.z += v.z * sc; acc.w += v.w * sc;
            }
        }
        uint32_t h0, l0, h1, l1;
        split2(acc.x * di, acc.y * di, h0, l0);
        split2(acc.z * di, acc.w * di, h1, l1);
        const size_t eo = (size_t)node * sNext + c * 4;
        *reinterpret_cast<uint2*>(Ah + eo) = make_uint2(h0, h1);
        *reinterpret_cast<uint2*>(Al + eo) = make_uint2(l0, l1);
    }
}

// ================= gather_post =================
__global__ __launch_bounds__(256)
void gather_post(const float* __restrict__ t, const int* __restrict__ off,
                 const int* __restrict__ csc, int N4, int cpn,
                 __nv_bfloat16* __restrict__ Ah, __nv_bfloat16* __restrict__ Al, int sNext,
                 const float* __restrict__ bias, const float* __restrict__ dinv_in,
                 const float* __restrict__ dinv_out, float* __restrict__ outF) {
    const int gw = blockIdx.x * 8 + (threadIdx.x >> 5);
    const int lane = threadIdx.x & 31;
    const int node = gw / cpn, chunk = gw - node * cpn;
    if (node >= N_NODES) return;
    const int c = chunk * 32 + lane;

    const float4* t4 = (const float4*)t;
    const int beg = off[node], end = off[node + 1];
    float4 acc = make_float4(0.f, 0.f, 0.f, 0.f);
    for (int j = beg; j < end; j++) {
        const int s = csc[j];
        float4 v = t4[(size_t)s * N4 + c];
        acc.x += v.x; acc.y += v.y; acc.z += v.z; acc.w += v.w;
    }
    const float di = dinv_in[node];
    const float dv = dinv_out[node];
    const float4 b = ((const float4*)bias)[c];
    float v0 = fmaf(acc.x, di, b.x);
    float v1 = fmaf(acc.y, di, b.y);
    float v2 = fmaf(acc.z, di, b.z);
    float v3 = fmaf(acc.w, di, b.w);
    v0 = ((v0 < 0.f) ? 0.01f * v0 : v0) * dv;
    v1 = ((v1 < 0.f) ? 0.01f * v1 : v1) * dv;
    v2 = ((v2 < 0.f) ? 0.01f * v2 : v2) * dv;
    v3 = ((v3 < 0.f) ? 0.01f * v3 : v3) * dv;

    if (outF) {
        ((float4*)outF)[(size_t)node * N4 + c] = make_float4(v0, v1, v2, v3);
    } else {
        uint32_t h0, l0, h1, l1;
        split2(v0, v1, h0, l0);
        split2(v2, v3, h1, l1);
        const size_t eo = (size_t)node * sNext + c * 4;
        *reinterpret_cast<uint2*>(Ah + eo) = make_uint2(h0, h1);
        *reinterpret_cast<uint2*>(Al + eo) = make_uint2(l0, l1);
    }
}

// ================= launch =================
extern "C" void kernel_launch(void* const* d_in, const int* in_sizes, int n_in,
                              void* d_out, int out_size) {
    const float* x = (const float*)d_in[0];
    const int* ei = (const int*)d_in[1];   // int32 (JAX x64 disabled)
    const float* W[5] = {(const float*)d_in[2], (const float*)d_in[4], (const float*)d_in[6],
                         (const float*)d_in[8], (const float*)d_in[10]};
    const float* B[5] = {(const float*)d_in[3], (const float*)d_in[5], (const float*)d_in[7],
                         (const float*)d_in[9], (const float*)d_in[11]};

    const int M = N_NODES;
    const int nE = N_EDGES;
    const int* src = ei;
    const int* dstp = ei + nE;

    float *tP, *yP, *doutP, *dinP;
    __nv_bfloat16 *Ah0, *Al0, *Ah1, *Al1, *WhP, *WlP;
    int *idegP, *odegP, *offP, *curP, *cscP, *bsumP;
    cudaGetSymbolAddress((void**)&tP, g_t);
    cudaGetSymbolAddress((void**)&yP, g_y);
    cudaGetSymbolAddress((void**)&Ah0, g_Ah0);
    cudaGetSymbolAddress((void**)&Al0, g_Al0);
    cudaGetSymbolAddress((void**)&Ah1, g_Ah1);
    cudaGetSymbolAddress((void**)&Al1, g_Al1);
    cudaGetSymbolAddress((void**)&WhP, g_Wh);
    cudaGetSymbolAddress((void**)&WlP, g_Wl);
    cudaGetSymbolAddress((void**)&doutP, g_dinv_out);
    cudaGetSymbolAddress((void**)&dinP, g_dinv_in);
    cudaGetSymbolAddress((void**)&idegP, g_ideg);
    cudaGetSymbolAddress((void**)&odegP, g_odeg);
    cudaGetSymbolAddress((void**)&offP, g_off);
    cudaGetSymbolAddress((void**)&curP, g_cur);
    cudaGetSymbolAddress((void**)&cscP, g_csc);
    cudaGetSymbolAddress((void**)&bsumP, g_bsum);

    cudaFuncSetAttribute(gemm_mma, cudaFuncAttributeMaxDynamicSharedMemorySize, SMEM_TOTAL_B);

    // degrees + parallel scan + CSC fill
    hist_kernel<<<(nE + 255) / 256, 256>>>(src, dstp, odegP, idegP, nE);
    blocksum_kernel<<<SCAN_NB, SCAN_BS>>>(idegP, bsumP);
    scanpart_kernel<<<1, 256>>>(bsumP, SCAN_NB);
    offsets_dinv_kernel<<<SCAN_NB, SCAN_BS>>>(idegP, odegP, bsumP, offP, curP, doutP, dinP);
    fill_kernel<<<(nE + 255) / 256, 256>>>(src, dstp, curP, cscP, nE);
    // layer-1 pre-aggregation (K=300 -> split A0, stride 320)
    gather_pre<<<(M + 7) / 8, 256>>>(x, doutP, offP, cscP, 75, 80, Ah0, Al0, 320, dinP);
    // all weight planes
    prep_w_all<<<640, 256>>>(W[0], W[1], W[2], W[3], W[4], WhP, WlP);

    // Layer 1 GEMM (K=320, N=1024) epilogue -> split A1
    {
        dim3 grid(1024 / 128, M_PAD / 128);
        gemm_mma<<<grid, 256, SMEM_TOTAL_B>>>(Ah0, Al0, WhP + WOFF0, WlP + WOFF0, nullptr,
                                              M, 1024, 320, 1, B[0], doutP, Ah1, Al1, 1024);
    }
    // Layer 2 (K=1024, N=512)
    {
        dim3 grid(512 / 128, M_PAD / 128);
        gemm_mma<<<grid, 256, SMEM_TOTAL_B>>>(Ah1, Al1, WhP + WOFF1, WlP + WOFF1, tP,
                                              M, 512, 1024, 0, nullptr, nullptr, nullptr, nullptr, 0);
    }
    gather_post<<<(M * 4 + 7) / 8, 256>>>(tP, offP, cscP, 128, 4, Ah0, Al0, 512,
                                          B[1], dinP, doutP, nullptr);
    // Layer 3 (K=512, N=256)
    {
        dim3 grid(256 / 128, M_PAD / 128);
        gemm_mma<<<grid, 256, SMEM_TOTAL_B>>>(Ah0, Al0, WhP + WOFF2, WlP + WOFF2, tP,
                                              M, 256, 512, 0, nullptr, nullptr, nullptr, nullptr, 0);
    }
    gather_post<<<(M * 2 + 7) / 8, 256>>>(tP, offP, cscP, 64, 2, Ah1, Al1, 256,
                                          B[2], dinP, doutP, nullptr);
    // Layer 4 (K=256, N=128) -> fp32 y
    {
        dim3 grid(128 / 128, M_PAD / 128);
        gemm_mma<<<grid, 256, SMEM_TOTAL_B>>>(Ah1, Al1, WhP + WOFF3, WlP + WOFF3, tP,
                                              M, 128, 256, 0, nullptr, nullptr, nullptr, nullptr, 0);
    }
    gather_post<<<(M + 7) / 8, 256>>>(tP, offP, cscP, 32, 1, nullptr, nullptr, 0,
                                      B[3], dinP, doutP, yP);
    // Layer 5 (aggregate-first, K=128, N=2048) -> d_out
    gather_pre<<<(M + 7) / 8, 256>>>(yP, nullptr, offP, cscP, 32, 32, Ah0, Al0, 128, dinP);
    {
        dim3 grid(2048 / 128, M_PAD / 128);
        gemm_mma<<<grid, 256, SMEM_TOTAL_B>>>(Ah0, Al0, WhP + WOFF4, WlP + WOFF4, (float*)d_out,
                                              M, 2048, 128, 2, B[4], nullptr, nullptr, nullptr, 0);
    }
    // restore degree arrays for next replay
    cleanup_kernel<<<(M + 255) / 256, 256>>>(idegP, odegP);
}

// round 14
// speedup vs baseline: 1.6351x; 1.4882x over previous
#include <cuda_runtime.h>
#include <cuda_bf16.h>
#include <cuda_fp16.h>
#include <cstdint>

// ---------------- problem constants ----------------
#define N_NODES 50000
#define N_EDGES 250000
#define M_PAD 50048           // 391 * 128
// dims: 300 -> 1024 -> 512 -> 256 -> 128 -> 2048

// ---------------- static device scratch ----------------
// __device__ globals load zeroed; g_ideg/g_odeg are re-zeroed at the END of
// each replay (cleanup_kernel) so every graph replay starts from zero.
// A/W planes hold raw fp16 bits (declared as 16-bit storage).
__device__ __align__(256) float g_t[(size_t)N_NODES * 512];             // GEMM fp32 out (layers 2-4)
__device__ __align__(256) float g_y[(size_t)N_NODES * 128];             // layer-4 activation fp32
__device__ __align__(256) __half g_Ah0[(size_t)M_PAD * 1024];           // split A ping (fp16 hi)
__device__ __align__(256) __half g_Al0[(size_t)M_PAD * 1024];           // (fp16 lo)
__device__ __align__(256) __half g_Ah1[(size_t)M_PAD * 1024];           // split A pong
__device__ __align__(256) __half g_Al1[(size_t)M_PAD * 1024];
__device__ __align__(256) __half g_Wf[1277952];                         // all layers, single fp16 plane
__device__ __align__(256) float g_dinv_out[N_NODES];
__device__ __align__(256) float g_dinv_in[N_NODES];
// CSC structures
__device__ __align__(256) int g_ideg[N_NODES];   // zero at entry
__device__ __align__(256) int g_odeg[N_NODES];   // zero at entry
__device__ __align__(256) int g_off[N_NODES + 4];
__device__ __align__(256) int g_cur[N_NODES];
__device__ __align__(256) int g_csc[N_EDGES];
__device__ __align__(256) int g_bsum[128];

// per-layer W plane offsets (fp16 elements)
#define WOFF0 0
#define WOFF1 327680
#define WOFF2 851968
#define WOFF3 983040
#define WOFF4 1015808

// ================= helpers =================
__device__ __forceinline__ uint32_t smem_u32(const void* p) {
    uint32_t a;
    asm("{ .reg .u64 t; cvta.to.shared.u64 t, %1; cvt.u32.u64 %0, t; }" : "=r"(a) : "l"(p));
    return a;
}

__device__ __forceinline__ void ldm_x4(uint32_t& r0, uint32_t& r1, uint32_t& r2, uint32_t& r3,
                                       uint32_t addr) {
    asm volatile("ldmatrix.sync.aligned.m8n8.x4.shared.b16 {%0,%1,%2,%3}, [%4];"
                 : "=r"(r0), "=r"(r1), "=r"(r2), "=r"(r3) : "r"(addr));
}

__device__ __forceinline__ void mma_f16(float* d, const uint32_t* a, const uint32_t* b) {
    asm volatile("mma.sync.aligned.m16n8k16.row.col.f32.f16.f16.f32 "
                 "{%0,%1,%2,%3}, {%4,%5,%6,%7}, {%8,%9}, {%0,%1,%2,%3};"
                 : "+f"(d[0]), "+f"(d[1]), "+f"(d[2]), "+f"(d[3])
                 : "r"(a[0]), "r"(a[1]), "r"(a[2]), "r"(a[3]), "r"(b[0]), "r"(b[1]));
}

// fp32 -> fp16 hi/lo split, packed pair (low 16 bits = even-k element)
__device__ __forceinline__ void split2h(float a, float b, uint32_t& hi, uint32_t& lo) {
    __half ah = __float2half_rn(a);
    __half bh = __float2half_rn(b);
    __half al = __float2half_rn(a - __half2float(ah));
    __half bl = __float2half_rn(b - __half2float(bh));
    hi = ((uint32_t)__half_as_ushort(bh) << 16) | (uint32_t)__half_as_ushort(ah);
    lo = ((uint32_t)__half_as_ushort(bl) << 16) | (uint32_t)__half_as_ushort(al);
}

// fp32 pair -> packed fp16 pair
__device__ __forceinline__ uint32_t pack2h(float a, float b) {
    __half ah = __float2half_rn(a);
    __half bh = __float2half_rn(b);
    return ((uint32_t)__half_as_ushort(bh) << 16) | (uint32_t)__half_as_ushort(ah);
}

// ================= pipelined fp16x2 mma.sync GEMM (128x128, 2-stage) =================
// C = (Ah+Al) @ Wf^T.  A planes fp16 [M_PAD, sA], Wf fp16 [N, sA] (k-major rows).
// Single __syncthreads per k-tile (barrier admits stage kt AND proves buffer
// (kt+1)&1's readers from iteration kt-1 are done).
// Epilogue modes:
//  0: C[m][n] = d                         (fp32 t for gather_post)
//  1: A'(next) = split(leaky(d + bias[n]) * dout[m])   (stride sNext)
//  2: C[m][n] = d + bias[n]               (final output)
#define APAD 40                 // fp16 row stride in smem (80B)
#define TILE_B 10240            // 128*40*2 bytes per tile
#define STAGE_B 30720           // 3 tiles (Ah, Al, Wf)
#define SMEM_TOTAL_B 61440      // 2 stages

__global__ __launch_bounds__(256)
void gemm_mma(const __half* __restrict__ Ah, const __half* __restrict__ Al,
              const __half* __restrict__ Wf,
              float* __restrict__ C, int M, int N, int sA,
              int mode, const float* __restrict__ bias, const float* __restrict__ dout,
              __half* __restrict__ oAh, __half* __restrict__ oAl, int sNext) {
    extern __shared__ __half dsm[];
    const uint32_t sbase = smem_u32(dsm);

    const int tid = threadIdx.x, lane = tid & 31, wid = tid >> 5;
    const int bm = blockIdx.y * 128, bn = blockIdx.x * 128;
    const int wm = (wid >> 1) * 32, wn = (wid & 1) * 64;
    const int nkt = sA >> 5;

    const int g = lane >> 3, l8 = lane & 7;
    const uint32_t aoff = (uint32_t)(((g & 1) * 8 + l8) * APAD + (g >> 1) * 8);
    const uint32_t boff = (uint32_t)(((g >> 1) * 8 + l8) * APAD + (g & 1) * 8);

    // 1536 16B-chunks per stage / 256 threads = 6 per thread
    auto load_stage = [&](int kt, int st) {
        const int k0 = kt << 5;
        #pragma unroll
        for (int it = 0; it < 6; it++) {
            const int idx = it * 256 + tid;
            const int t = idx >> 9, rc = idx & 511;
            const int r = rc >> 2, c = rc & 3;
            const __half* gsrc;
            if (t == 0)      gsrc = Ah + (size_t)(bm + r) * sA + k0 + c * 8;
            else if (t == 1) gsrc = Al + (size_t)(bm + r) * sA + k0 + c * 8;
            else             gsrc = Wf + (size_t)(bn + r) * sA + k0 + c * 8;
            const uint32_t d = sbase + st * STAGE_B + t * TILE_B + r * 80 + c * 16;
            asm volatile("cp.async.ca.shared.global [%0], [%1], 16;" :: "r"(d), "l"(gsrc));
        }
    };

    float acc[2][8][4] = {};

    load_stage(0, 0);
    asm volatile("cp.async.commit_group;" ::: "memory");

    for (int kt = 0; kt < nkt; kt++) {
        const int st = kt & 1;

        asm volatile("cp.async.wait_group 0;" ::: "memory");   // stage kt arrived
        __syncthreads();                                        // + buf st^1 readers done

        if (kt + 1 < nkt) {
            load_stage(kt + 1, st ^ 1);
            asm volatile("cp.async.commit_group;" ::: "memory");
        }

        const uint32_t sAh_u = sbase + st * STAGE_B;
        const uint32_t sAl_u = sAh_u + TILE_B;
        const uint32_t sWf_u = sAh_u + 2 * TILE_B;

        #pragma unroll
        for (int ks = 0; ks < 2; ks++) {
            uint32_t ah[2][4], al[2][4];
            #pragma unroll
            for (int mb = 0; mb < 2; mb++) {
                const uint32_t off = (aoff + (uint32_t)(wm + mb * 16) * APAD + ks * 16) * 2;
                ldm_x4(ah[mb][0], ah[mb][1], ah[mb][2], ah[mb][3], sAh_u + off);
                ldm_x4(al[mb][0], al[mb][1], al[mb][2], al[mb][3], sAl_u + off);
            }
            #pragma unroll
            for (int nbp = 0; nbp < 4; nbp++) {
                const uint32_t off = (boff + (uint32_t)(wn + nbp * 16) * APAD + ks * 16) * 2;
                uint32_t wf[4];
                ldm_x4(wf[0], wf[1], wf[2], wf[3], sWf_u + off);
                #pragma unroll
                for (int h = 0; h < 2; h++) {
                    #pragma unroll
                    for (int mb = 0; mb < 2; mb++) {
                        float* d = acc[mb][nbp * 2 + h];
                        mma_f16(d, ah[mb], wf + h * 2);
                        mma_f16(d, al[mb], wf + h * 2);
                    }
                }
            }
        }
    }

    const int mrow = lane >> 2, ncol = (lane & 3) * 2;
    #pragma unroll
    for (int mb = 0; mb < 2; mb++) {
        const int m0 = bm + wm + mb * 16 + mrow;
        float dv0 = 0.f, dv1 = 0.f;
        if (mode == 1) {
            if (m0 < M) dv0 = dout[m0];
            if (m0 + 8 < M) dv1 = dout[m0 + 8];
        }
        #pragma unroll
        for (int nb = 0; nb < 8; nb++) {
            const float* d = acc[mb][nb];
            const int n = bn + wn + nb * 8 + ncol;
            if (mode == 0) {
                if (m0 < M)
                    *reinterpret_cast<float2*>(C + (size_t)m0 * N + n) = make_float2(d[0], d[1]);
                if (m0 + 8 < M)
                    *reinterpret_cast<float2*>(C + (size_t)(m0 + 8) * N + n) = make_float2(d[2], d[3]);
            } else if (mode == 2) {
                const float b0 = bias[n], b1 = bias[n + 1];
                if (m0 < M)
                    *reinterpret_cast<float2*>(C + (size_t)m0 * N + n) = make_float2(d[0] + b0, d[1] + b1);
                if (m0 + 8 < M)
                    *reinterpret_cast<float2*>(C + (size_t)(m0 + 8) * N + n) = make_float2(d[2] + b0, d[3] + b1);
            } else {
                const float b0 = bias[n], b1 = bias[n + 1];
                if (m0 < M) {
                    float v0 = d[0] + b0, v1 = d[1] + b1;
                    v0 = ((v0 < 0.f) ? 0.01f * v0 : v0) * dv0;
                    v1 = ((v1 < 0.f) ? 0.01f * v1 : v1) * dv0;
                    uint32_t hi, lo; split2h(v0, v1, hi, lo);
                    *reinterpret_cast<uint32_t*>(oAh + (size_t)m0 * sNext + n) = hi;
                    *reinterpret_cast<uint32_t*>(oAl + (size_t)m0 * sNext + n) = lo;
                }
                if (m0 + 8 < M) {
                    float v0 = d[2] + b0, v1 = d[3] + b1;
                    v0 = ((v0 < 0.f) ? 0.01f * v0 : v0) * dv1;
                    v1 = ((v1 < 0.f) ? 0.01f * v1 : v1) * dv1;
                    uint32_t hi, lo; split2h(v0, v1, hi, lo);
                    *reinterpret_cast<uint32_t*>(oAh + (size_t)(m0 + 8) * sNext + n) = hi;
                    *reinterpret_cast<uint32_t*>(oAl + (size_t)(m0 + 8) * sNext + n) = lo;
                }
            }
        }
    }
}

// ================= fused W prep: all 5 layers, single fp16 plane =================
__global__ void prep_w_all(const float* __restrict__ W0, const float* __restrict__ W1,
                           const float* __restrict__ W2, const float* __restrict__ W3,
                           const float* __restrict__ W4,
                           __half* __restrict__ Wf) {
    const int starts[6] = {0, 163840, 425984, 491520, 507904, 638976};
    const int Ks[5]     = {300, 1024, 512, 256, 128};
    const int Ns[5]     = {1024, 512, 256, 128, 2048};
    const int Kpads[5]  = {320, 1024, 512, 256, 128};
    const int woffs[5]  = {WOFF0, WOFF1, WOFF2, WOFF3, WOFF4};
    const float* Ws[5]  = {W0, W1, W2, W3, W4};

    int idx = blockIdx.x * blockDim.x + threadIdx.x;
    int stride = gridDim.x * blockDim.x;
    for (; idx < 638976; idx += stride) {
        int l = 0;
        #pragma unroll
        for (int q = 1; q < 5; q++) if (idx >= starts[q]) l = q;
        const int p = idx - starts[l];
        const int Kp2 = Kpads[l] >> 1;
        const int n = p / Kp2, pk = p - n * Kp2;
        const int k = pk * 2;
        const int K = Ks[l], N = Ns[l];
        float w0 = 0.f, w1 = 0.f;
        if (k < K)     w0 = Ws[l][(size_t)k * N + n];
        if (k + 1 < K) w1 = Ws[l][(size_t)(k + 1) * N + n];
        ((uint32_t*)(Wf + woffs[l]))[p] = pack2h(w0, w1);
    }
}

// ================= CSC build (parallel scan) =================
__global__ void hist_kernel(const int* __restrict__ src, const int* __restrict__ dst,
                            int* __restrict__ odeg, int* __restrict__ ideg, int nE) {
    int e = blockIdx.x * blockDim.x + threadIdx.x;
    if (e >= nE) return;
    int s = src[e], d = dst[e];
    if ((unsigned)s < N_NODES) atomicAdd(&odeg[s], 1);
    if ((unsigned)d < N_NODES) atomicAdd(&ideg[d], 1);
}

#define SCAN_BS 512
#define SCAN_NB ((N_NODES + SCAN_BS - 1) / SCAN_BS)  // 98

__global__ void blocksum_kernel(const int* __restrict__ deg, int* __restrict__ bsum) {
    __shared__ int sh[SCAN_BS];
    int i = blockIdx.x * SCAN_BS + threadIdx.x;
    sh[threadIdx.x] = (i < N_NODES) ? deg[i] : 0;
    __syncthreads();
    for (int s = SCAN_BS / 2; s > 0; s >>= 1) {
        if (threadIdx.x < s) sh[threadIdx.x] += sh[threadIdx.x + s];
        __syncthreads();
    }
    if (threadIdx.x == 0) bsum[blockIdx.x] = sh[0];
}

__global__ void scanpart_kernel(int* __restrict__ bsum, int nb) {
    __shared__ int sh[256];
    int t = threadIdx.x;
    int v = (t < nb) ? bsum[t] : 0;
    sh[t] = v;
    __syncthreads();
    for (int s = 1; s < 256; s <<= 1) {
        int add = (t >= s) ? sh[t - s] : 0;
        __syncthreads();
        sh[t] += add;
        __syncthreads();
    }
    if (t < nb) bsum[t] = sh[t] - v;  // exclusive
}

__global__ void offsets_dinv_kernel(const int* __restrict__ ideg, const int* __restrict__ odeg,
                                    const int* __restrict__ bsum,
                                    int* __restrict__ off, int* __restrict__ cur,
                                    float* __restrict__ dout, float* __restrict__ din) {
    __shared__ int sh[SCAN_BS];
    int t = threadIdx.x;
    int i = blockIdx.x * SCAN_BS + t;
    int v = (i < N_NODES) ? ideg[i] : 0;
    if (i < N_NODES) {
        dout[i] = rsqrtf(fmaxf((float)odeg[i], 1.0f));
        din[i]  = rsqrtf(fmaxf((float)v, 1.0f));
    }
    sh[t] = v;
    __syncthreads();
    for (int s = 1; s < SCAN_BS; s <<= 1) {
        int add = (t >= s) ? sh[t - s] : 0;
        __syncthreads();
        sh[t] += add;
        __syncthreads();
    }
    if (i < N_NODES) {
        int excl = sh[t] - v + bsum[blockIdx.x];
        off[i] = excl;
        cur[i] = excl;
        if (i == N_NODES - 1) off[N_NODES] = excl + v;
    }
}

__global__ void fill_kernel(const int* __restrict__ src, const int* __restrict__ dst,
                            int* __restrict__ cur, int* __restrict__ csc, int nE) {
    int e = blockIdx.x * blockDim.x + threadIdx.x;
    if (e >= nE) return;
    int s = src[e], d = dst[e];
    if ((unsigned)s >= N_NODES || (unsigned)d >= N_NODES) return;
    int pos = atomicAdd(&cur[d], 1);
    csc[pos] = s;
}

__global__ void cleanup_kernel(int* __restrict__ ideg, int* __restrict__ odeg) {
    int i = blockIdx.x * blockDim.x + threadIdx.x;
    if (i < N_NODES) { ideg[i] = 0; odeg[i] = 0; }
}

// ================= gather_pre: u = dinv_in ⊙ S (opt dout ⊙) y  -> split fp16 =================
__global__ __launch_bounds__(256)
void gather_pre(const float* __restrict__ y, const float* __restrict__ dout,
                const int* __restrict__ off, const int* __restrict__ csc,
                int K4, int Kpad4,
                __half* __restrict__ Ah, __half* __restrict__ Al, int sNext,
                const float* __restrict__ dinv_in) {
    const int node = blockIdx.x * 8 + (threadIdx.x >> 5);
    if (node >= N_NODES) return;
    const int lane = threadIdx.x & 31;
    const int beg = off[node], end = off[node + 1];
    const float di = dinv_in[node];
    const float4* y4 = (const float4*)y;

    for (int c = lane; c < Kpad4; c += 32) {
        float4 acc = make_float4(0.f, 0.f, 0.f, 0.f);
        if (c < K4) {
            for (int j = beg; j < end; j++) {
                const int s = csc[j];
                float4 v = y4[(size_t)s * K4 + c];
                const float sc = dout ? dout[s] : 1.0f;
                acc.x += v.x * sc; acc.y += v.y * sc; acc.z += v.z * sc; acc.w += v.w * sc;
            }
        }
        uint32_t h0, l0, h1, l1;
        split2h(acc.x * di, acc.y * di, h0, l0);
        split2h(acc.z * di, acc.w * di, h1, l1);
        const size_t eo = (size_t)node * sNext + c * 4;
        *reinterpret_cast<uint2*>(Ah + eo) = make_uint2(h0, h1);
        *reinterpret_cast<uint2*>(Al + eo) = make_uint2(l0, l1);
    }
}

// ================= gather_post =================
__global__ __launch_bounds__(256)
void gather_post(const float* __restrict__ t, const int* __restrict__ off,
                 const int* __restrict__ csc, int N4, int cpn,
                 __half* __restrict__ Ah, __half* __restrict__ Al, int sNext,
                 const float* __restrict__ bias, const float* __restrict__ dinv_in,
                 const float* __restrict__ dinv_out, float* __restrict__ outF) {
    const int gw = blockIdx.x * 8 + (threadIdx.x >> 5);
    const int lane = threadIdx.x & 31;
    const int node = gw / cpn, chunk = gw - node * cpn;
    if (node >= N_NODES) return;
    const int c = chunk * 32 + lane;

    const float4* t4 = (const float4*)t;
    const int beg = off[node], end = off[node + 1];
    float4 acc = make_float4(0.f, 0.f, 0.f, 0.f);
    for (int j = beg; j < end; j++) {
        const int s = csc[j];
        float4 v = t4[(size_t)s * N4 + c];
        acc.x += v.x; acc.y += v.y; acc.z += v.z; acc.w += v.w;
    }
    const float di = dinv_in[node];
    const float dv = dinv_out[node];
    const float4 b = ((const float4*)bias)[c];
    float v0 = fmaf(acc.x, di, b.x);
    float v1 = fmaf(acc.y, di, b.y);
    float v2 = fmaf(acc.z, di, b.z);
    float v3 = fmaf(acc.w, di, b.w);
    v0 = ((v0 < 0.f) ? 0.01f * v0 : v0) * dv;
    v1 = ((v1 < 0.f) ? 0.01f * v1 : v1) * dv;
    v2 = ((v2 < 0.f) ? 0.01f * v2 : v2) * dv;
    v3 = ((v3 < 0.f) ? 0.01f * v3 : v3) * dv;

    if (outF) {
        ((float4*)outF)[(size_t)node * N4 + c] = make_float4(v0, v1, v2, v3);
    } else {
        uint32_t h0, l0, h1, l1;
        split2h(v0, v1, h0, l0);
        split2h(v2, v3, h1, l1);
        const size_t eo = (size_t)node * sNext + c * 4;
        *reinterpret_cast<uint2*>(Ah + eo) = make_uint2(h0, h1);
        *reinterpret_cast<uint2*>(Al + eo) = make_uint2(l0, l1);
    }
}

// ================= launch =================
extern "C" void kernel_launch(void* const* d_in, const int* in_sizes, int n_in,
                              void* d_out, int out_size) {
    const float* x = (const float*)d_in[0];
    const int* ei = (const int*)d_in[1];   // int32 (JAX x64 disabled)
    const float* W[5] = {(const float*)d_in[2], (const float*)d_in[4], (const float*)d_in[6],
                         (const float*)d_in[8], (const float*)d_in[10]};
    const float* B[5] = {(const float*)d_in[3], (const float*)d_in[5], (const float*)d_in[7],
                         (const float*)d_in[9], (const float*)d_in[11]};

    const int M = N_NODES;
    const int nE = N_EDGES;
    const int* src = ei;
    const int* dstp = ei + nE;

    float *tP, *yP, *doutP, *dinP;
    __half *Ah0, *Al0, *Ah1, *Al1, *WfP;
    int *idegP, *odegP, *offP, *curP, *cscP, *bsumP;
    cudaGetSymbolAddress((void**)&tP, g_t);
    cudaGetSymbolAddress((void**)&yP, g_y);
    cudaGetSymbolAddress((void**)&Ah0, g_Ah0);
    cudaGetSymbolAddress((void**)&Al0, g_Al0);
    cudaGetSymbolAddress((void**)&Ah1, g_Ah1);
    cudaGetSymbolAddress((void**)&Al1, g_Al1);
    cudaGetSymbolAddress((void**)&WfP, g_Wf);
    cudaGetSymbolAddress((void**)&doutP, g_dinv_out);
    cudaGetSymbolAddress((void**)&dinP, g_dinv_in);
    cudaGetSymbolAddress((void**)&idegP, g_ideg);
    cudaGetSymbolAddress((void**)&odegP, g_odeg);
    cudaGetSymbolAddress((void**)&offP, g_off);
    cudaGetSymbolAddress((void**)&curP, g_cur);
    cudaGetSymbolAddress((void**)&cscP, g_csc);
    cudaGetSymbolAddress((void**)&bsumP, g_bsum);

    cudaFuncSetAttribute(gemm_mma, cudaFuncAttributeMaxDynamicSharedMemorySize, SMEM_TOTAL_B);

    // degrees + parallel scan + CSC fill
    hist_kernel<<<(nE + 255) / 256, 256>>>(src, dstp, odegP, idegP, nE);
    blocksum_kernel<<<SCAN_NB, SCAN_BS>>>(idegP, bsumP);
    scanpart_kernel<<<1, 256>>>(bsumP, SCAN_NB);
    offsets_dinv_kernel<<<SCAN_NB, SCAN_BS>>>(idegP, odegP, bsumP, offP, curP, doutP, dinP);
    fill_kernel<<<(nE + 255) / 256, 256>>>(src, dstp, curP, cscP, nE);
    // layer-1 pre-aggregation (K=300 -> split A0, stride 320)
    gather_pre<<<(M + 7) / 8, 256>>>(x, doutP, offP, cscP, 75, 80, Ah0, Al0, 320, dinP);
    // all weight planes (single fp16 plane per layer)
    prep_w_all<<<640, 256>>>(W[0], W[1], W[2], W[3], W[4], WfP);

    // Layer 1 GEMM (K=320, N=1024) epilogue -> split A1
    {
        dim3 grid(1024 / 128, M_PAD / 128);
        gemm_mma<<<grid, 256, SMEM_TOTAL_B>>>(Ah0, Al0, WfP + WOFF0, nullptr,
                                              M, 1024, 320, 1, B[0], doutP, Ah1, Al1, 1024);
    }
    // Layer 2 (K=1024, N=512)
    {
        dim3 grid(512 / 128, M_PAD / 128);
        gemm_mma<<<grid, 256, SMEM_TOTAL_B>>>(Ah1, Al1, WfP + WOFF1, tP,
                                              M, 512, 1024, 0, nullptr, nullptr, nullptr, nullptr, 0);
    }
    gather_post<<<(M * 4 + 7) / 8, 256>>>(tP, offP, cscP, 128, 4, Ah0, Al0, 512,
                                          B[1], dinP, doutP, nullptr);
    // Layer 3 (K=512, N=256)
    {
        dim3 grid(256 / 128, M_PAD / 128);
        gemm_mma<<<grid, 256, SMEM_TOTAL_B>>>(Ah0, Al0, WfP + WOFF2, tP,
                                              M, 256, 512, 0, nullptr, nullptr, nullptr, nullptr, 0);
    }
    gather_post<<<(M * 2 + 7) / 8, 256>>>(tP, offP, cscP, 64, 2, Ah1, Al1, 256,
                                          B[2], dinP, doutP, nullptr);
    // Layer 4 (K=256, N=128) -> fp32 y
    {
        dim3 grid(128 / 128, M_PAD / 128);
        gemm_mma<<<grid, 256, SMEM_TOTAL_B>>>(Ah1, Al1, WfP + WOFF3, tP,
                                              M, 128, 256, 0, nullptr, nullptr, nullptr, nullptr, 0);
    }
    gather_post<<<(M + 7) / 8, 256>>>(tP, offP, cscP, 32, 1, nullptr, nullptr, 0,
                                      B[3], dinP, doutP, yP);
    // Layer 5 (aggregate-first, K=128, N=2048) -> d_out
    gather_pre<<<(M + 7) / 8, 256>>>(yP, nullptr, offP, cscP, 32, 32, Ah0, Al0, 128, dinP);
    {
        dim3 grid(2048 / 128, M_PAD / 128);
        gemm_mma<<<grid, 256, SMEM_TOTAL_B>>>(Ah0, Al0, WfP + WOFF4, (float*)d_out,
                                              M, 2048, 128, 2, B[4], nullptr, nullptr, nullptr, 0);
    }
    // restore degree arrays for next replay
    cleanup_kernel<<<(M + 255) / 256, 256>>>(idegP, odegP);
}

// round 15
// speedup vs baseline: 2.1733x; 1.3292x over previous
#include <cuda_runtime.h>
#include <cuda_bf16.h>
#include <cuda_fp16.h>
#include <cstdint>

// ---------------- problem constants ----------------
#define N_NODES 50000
#define N_EDGES 250000
#define M_PAD 50048           // 391 * 128
// dims: 300 -> 1024 -> 512 -> 256 -> 128 -> 2048

// ---------------- static device scratch ----------------
// __device__ globals load zeroed; g_ideg/g_odeg are re-zeroed at the END of
// each replay (cleanup_kernel) so every graph replay starts from zero.
__device__ __align__(256) float g_t[(size_t)N_NODES * 512];             // GEMM fp32 out (layers 2-4)
__device__ __align__(256) float g_y[(size_t)N_NODES * 128];             // layer-4 activation fp32
__device__ __align__(256) __half g_A0[(size_t)M_PAD * 1024];            // fp16 A ping
__device__ __align__(256) __half g_A1[(size_t)M_PAD * 1024];            // fp16 A pong
__device__ __align__(256) __half g_Wf[1277952];                         // all layers, fp16 W plane
__device__ __align__(256) float g_dinv_out[N_NODES];
__device__ __align__(256) float g_dinv_in[N_NODES];
// CSC structures
__device__ __align__(256) int g_ideg[N_NODES];   // zero at entry
__device__ __align__(256) int g_odeg[N_NODES];   // zero at entry
__device__ __align__(256) int g_off[N_NODES + 4];
__device__ __align__(256) int g_cur[N_NODES];
__device__ __align__(256) int g_csc[N_EDGES];
__device__ __align__(256) int g_bsum[128];

// per-layer W plane offsets (fp16 elements)
#define WOFF0 0
#define WOFF1 327680
#define WOFF2 851968
#define WOFF3 983040
#define WOFF4 1015808

// ================= helpers =================
__device__ __forceinline__ uint32_t smem_u32(const void* p) {
    uint32_t a;
    asm("{ .reg .u64 t; cvta.to.shared.u64 t, %1; cvt.u32.u64 %0, t; }" : "=r"(a) : "l"(p));
    return a;
}

__device__ __forceinline__ void ldm_x4(uint32_t& r0, uint32_t& r1, uint32_t& r2, uint32_t& r3,
                                       uint32_t addr) {
    asm volatile("ldmatrix.sync.aligned.m8n8.x4.shared.b16 {%0,%1,%2,%3}, [%4];"
                 : "=r"(r0), "=r"(r1), "=r"(r2), "=r"(r3) : "r"(addr));
}

__device__ __forceinline__ void mma_f16(float* d, const uint32_t* a, const uint32_t* b) {
    asm volatile("mma.sync.aligned.m16n8k16.row.col.f32.f16.f16.f32 "
                 "{%0,%1,%2,%3}, {%4,%5,%6,%7}, {%8,%9}, {%0,%1,%2,%3};"
                 : "+f"(d[0]), "+f"(d[1]), "+f"(d[2]), "+f"(d[3])
                 : "r"(a[0]), "r"(a[1]), "r"(a[2]), "r"(a[3]), "r"(b[0]), "r"(b[1]));
}

// fp32 pair -> packed fp16 pair (low 16 bits = first element)
__device__ __forceinline__ uint32_t pack2h(float a, float b) {
    __half ah = __float2half_rn(a);
    __half bh = __float2half_rn(b);
    return ((uint32_t)__half_as_ushort(bh) << 16) | (uint32_t)__half_as_ushort(ah);
}

// ================= pipelined fp16 mma.sync GEMM (128x128, 2-stage) =================
// C = A @ Wf^T.  A fp16 [M_PAD, sA], Wf fp16 [N, sA] (k-major rows), fp32 accum.
// Single __syncthreads per k-tile (barrier admits stage kt AND proves buffer
// (kt+1)&1's readers from iteration kt-1 are done).
// Epilogue modes:
//  0: C[m][n] = d                         (fp32 t for gather_post)
//  1: A'(next) = fp16(leaky(d + bias[n]) * dout[m])   (stride sNext)
//  2: C[m][n] = d + bias[n]               (final output)
#define APAD 40                 // fp16 row stride in smem (80B)
#define TILE_B 10240            // 128*40*2 bytes per tile
#define STAGE_B 20480           // 2 tiles (A, Wf)
#define SMEM_TOTAL_B 40960      // 2 stages

__global__ __launch_bounds__(256)
void gemm_mma(const __half* __restrict__ A, const __half* __restrict__ Wf,
              float* __restrict__ C, int M, int N, int sA,
              int mode, const float* __restrict__ bias, const float* __restrict__ dout,
              __half* __restrict__ oA, int sNext) {
    extern __shared__ __half dsm[];
    const uint32_t sbase = smem_u32(dsm);

    const int tid = threadIdx.x, lane = tid & 31, wid = tid >> 5;
    const int bm = blockIdx.y * 128, bn = blockIdx.x * 128;
    const int wm = (wid >> 1) * 32, wn = (wid & 1) * 64;
    const int nkt = sA >> 5;

    const int g = lane >> 3, l8 = lane & 7;
    const uint32_t aoff = (uint32_t)(((g & 1) * 8 + l8) * APAD + (g >> 1) * 8);
    const uint32_t boff = (uint32_t)(((g >> 1) * 8 + l8) * APAD + (g & 1) * 8);

    // 1024 16B-chunks per stage / 256 threads = 4 per thread
    auto load_stage = [&](int kt, int st) {
        const int k0 = kt << 5;
        #pragma unroll
        for (int it = 0; it < 4; it++) {
            const int idx = it * 256 + tid;
            const int t = idx >> 9, rc = idx & 511;
            const int r = rc >> 2, c = rc & 3;
            const __half* gsrc = (t == 0) ? A + (size_t)(bm + r) * sA + k0 + c * 8
                                          : Wf + (size_t)(bn + r) * sA + k0 + c * 8;
            const uint32_t d = sbase + st * STAGE_B + t * TILE_B + r * 80 + c * 16;
            asm volatile("cp.async.ca.shared.global [%0], [%1], 16;" :: "r"(d), "l"(gsrc));
        }
    };

    float acc[2][8][4] = {};

    load_stage(0, 0);
    asm volatile("cp.async.commit_group;" ::: "memory");

    for (int kt = 0; kt < nkt; kt++) {
        const int st = kt & 1;

        asm volatile("cp.async.wait_group 0;" ::: "memory");   // stage kt arrived
        __syncthreads();                                        // + buf st^1 readers done

        if (kt + 1 < nkt) {
            load_stage(kt + 1, st ^ 1);
            asm volatile("cp.async.commit_group;" ::: "memory");
        }

        const uint32_t sA_u = sbase + st * STAGE_B;
        const uint32_t sW_u = sA_u + TILE_B;

        #pragma unroll
        for (int ks = 0; ks < 2; ks++) {
            uint32_t ar[2][4];
            #pragma unroll
            for (int mb = 0; mb < 2; mb++) {
                const uint32_t off = (aoff + (uint32_t)(wm + mb * 16) * APAD + ks * 16) * 2;
                ldm_x4(ar[mb][0], ar[mb][1], ar[mb][2], ar[mb][3], sA_u + off);
            }
            #pragma unroll
            for (int nbp = 0; nbp < 4; nbp++) {
                const uint32_t off = (boff + (uint32_t)(wn + nbp * 16) * APAD + ks * 16) * 2;
                uint32_t wf[4];
                ldm_x4(wf[0], wf[1], wf[2], wf[3], sW_u + off);
                #pragma unroll
                for (int h = 0; h < 2; h++) {
                    #pragma unroll
                    for (int mb = 0; mb < 2; mb++) {
                        mma_f16(acc[mb][nbp * 2 + h], ar[mb], wf + h * 2);
                    }
                }
            }
        }
    }

    const int mrow = lane >> 2, ncol = (lane & 3) * 2;
    #pragma unroll
    for (int mb = 0; mb < 2; mb++) {
        const int m0 = bm + wm + mb * 16 + mrow;
        float dv0 = 0.f, dv1 = 0.f;
        if (mode == 1) {
            if (m0 < M) dv0 = dout[m0];
            if (m0 + 8 < M) dv1 = dout[m0 + 8];
        }
        #pragma unroll
        for (int nb = 0; nb < 8; nb++) {
            const float* d = acc[mb][nb];
            const int n = bn + wn + nb * 8 + ncol;
            if (mode == 0) {
                if (m0 < M)
                    *reinterpret_cast<float2*>(C + (size_t)m0 * N + n) = make_float2(d[0], d[1]);
                if (m0 + 8 < M)
                    *reinterpret_cast<float2*>(C + (size_t)(m0 + 8) * N + n) = make_float2(d[2], d[3]);
            } else if (mode == 2) {
                const float b0 = bias[n], b1 = bias[n + 1];
                if (m0 < M)
                    *reinterpret_cast<float2*>(C + (size_t)m0 * N + n) = make_float2(d[0] + b0, d[1] + b1);
                if (m0 + 8 < M)
                    *reinterpret_cast<float2*>(C + (size_t)(m0 + 8) * N + n) = make_float2(d[2] + b0, d[3] + b1);
            } else {
                const float b0 = bias[n], b1 = bias[n + 1];
                if (m0 < M) {
                    float v0 = d[0] + b0, v1 = d[1] + b1;
                    v0 = ((v0 < 0.f) ? 0.01f * v0 : v0) * dv0;
                    v1 = ((v1 < 0.f) ? 0.01f * v1 : v1) * dv0;
                    *reinterpret_cast<uint32_t*>(oA + (size_t)m0 * sNext + n) = pack2h(v0, v1);
                }
                if (m0 + 8 < M) {
                    float v0 = d[2] + b0, v1 = d[3] + b1;
                    v0 = ((v0 < 0.f) ? 0.01f * v0 : v0) * dv1;
                    v1 = ((v1 < 0.f) ? 0.01f * v1 : v1) * dv1;
                    *reinterpret_cast<uint32_t*>(oA + (size_t)(m0 + 8) * sNext + n) = pack2h(v0, v1);
                }
            }
        }
    }
}

// ================= fused W prep: all 5 layers, single fp16 plane =================
__global__ void prep_w_all(const float* __restrict__ W0, const float* __restrict__ W1,
                           const float* __restrict__ W2, const float* __restrict__ W3,
                           const float* __restrict__ W4,
                           __half* __restrict__ Wf) {
    const int starts[6] = {0, 163840, 425984, 491520, 507904, 638976};
    const int Ks[5]     = {300, 1024, 512, 256, 128};
    const int Ns[5]     = {1024, 512, 256, 128, 2048};
    const int Kpads[5]  = {320, 1024, 512, 256, 128};
    const int woffs[5]  = {WOFF0, WOFF1, WOFF2, WOFF3, WOFF4};
    const float* Ws[5]  = {W0, W1, W2, W3, W4};

    int idx = blockIdx.x * blockDim.x + threadIdx.x;
    int stride = gridDim.x * blockDim.x;
    for (; idx < 638976; idx += stride) {
        int l = 0;
        #pragma unroll
        for (int q = 1; q < 5; q++) if (idx >= starts[q]) l = q;
        const int p = idx - starts[l];
        const int Kp2 = Kpads[l] >> 1;
        const int n = p / Kp2, pk = p - n * Kp2;
        const int k = pk * 2;
        const int K = Ks[l], N = Ns[l];
        float w0 = 0.f, w1 = 0.f;
        if (k < K)     w0 = Ws[l][(size_t)k * N + n];
        if (k + 1 < K) w1 = Ws[l][(size_t)(k + 1) * N + n];
        ((uint32_t*)(Wf + woffs[l]))[p] = pack2h(w0, w1);
    }
}

// ================= CSC build (parallel scan) =================
__global__ void hist_kernel(const int* __restrict__ src, const int* __restrict__ dst,
                            int* __restrict__ odeg, int* __restrict__ ideg, int nE) {
    int e = blockIdx.x * blockDim.x + threadIdx.x;
    if (e >= nE) return;
    int s = src[e], d = dst[e];
    if ((unsigned)s < N_NODES) atomicAdd(&odeg[s], 1);
    if ((unsigned)d < N_NODES) atomicAdd(&ideg[d], 1);
}

#define SCAN_BS 512
#define SCAN_NB ((N_NODES + SCAN_BS - 1) / SCAN_BS)  // 98

__global__ void blocksum_kernel(const int* __restrict__ deg, int* __restrict__ bsum) {
    __shared__ int sh[SCAN_BS];
    int i = blockIdx.x * SCAN_BS + threadIdx.x;
    sh[threadIdx.x] = (i < N_NODES) ? deg[i] : 0;
    __syncthreads();
    for (int s = SCAN_BS / 2; s > 0; s >>= 1) {
        if (threadIdx.x < s) sh[threadIdx.x] += sh[threadIdx.x + s];
        __syncthreads();
    }
    if (threadIdx.x == 0) bsum[blockIdx.x] = sh[0];
}

__global__ void scanpart_kernel(int* __restrict__ bsum, int nb) {
    __shared__ int sh[256];
    int t = threadIdx.x;
    int v = (t < nb) ? bsum[t] : 0;
    sh[t] = v;
    __syncthreads();
    for (int s = 1; s < 256; s <<= 1) {
        int add = (t >= s) ? sh[t - s] : 0;
        __syncthreads();
        sh[t] += add;
        __syncthreads();
    }
    if (t < nb) bsum[t] = sh[t] - v;  // exclusive
}

__global__ void offsets_dinv_kernel(const int* __restrict__ ideg, const int* __restrict__ odeg,
                                    const int* __restrict__ bsum,
                                    int* __restrict__ off, int* __restrict__ cur,
                                    float* __restrict__ dout, float* __restrict__ din) {
    __shared__ int sh[SCAN_BS];
    int t = threadIdx.x;
    int i = blockIdx.x * SCAN_BS + t;
    int v = (i < N_NODES) ? ideg[i] : 0;
    if (i < N_NODES) {
        dout[i] = rsqrtf(fmaxf((float)odeg[i], 1.0f));
        din[i]  = rsqrtf(fmaxf((float)v, 1.0f));
    }
    sh[t] = v;
    __syncthreads();
    for (int s = 1; s < SCAN_BS; s <<= 1) {
        int add = (t >= s) ? sh[t - s] : 0;
        __syncthreads();
        sh[t] += add;
        __syncthreads();
    }
    if (i < N_NODES) {
        int excl = sh[t] - v + bsum[blockIdx.x];
        off[i] = excl;
        cur[i] = excl;
        if (i == N_NODES - 1) off[N_NODES] = excl + v;
    }
}

__global__ void fill_kernel(const int* __restrict__ src, const int* __restrict__ dst,
                            int* __restrict__ cur, int* __restrict__ csc, int nE) {
    int e = blockIdx.x * blockDim.x + threadIdx.x;
    if (e >= nE) return;
    int s = src[e], d = dst[e];
    if ((unsigned)s >= N_NODES || (unsigned)d >= N_NODES) return;
    int pos = atomicAdd(&cur[d], 1);
    csc[pos] = s;
}

__global__ void cleanup_kernel(int* __restrict__ ideg, int* __restrict__ odeg) {
    int i = blockIdx.x * blockDim.x + threadIdx.x;
    if (i < N_NODES) { ideg[i] = 0; odeg[i] = 0; }
}

// ================= gather_pre: u = dinv_in ⊙ S (opt dout ⊙) y  -> fp16 =================
__global__ __launch_bounds__(256)
void gather_pre(const float* __restrict__ y, const float* __restrict__ dout,
                const int* __restrict__ off, const int* __restrict__ csc,
                int K4, int Kpad4,
                __half* __restrict__ A, int sNext,
                const float* __restrict__ dinv_in) {
    const int node = blockIdx.x * 8 + (threadIdx.x >> 5);
    if (node >= N_NODES) return;
    const int lane = threadIdx.x & 31;
    const int beg = off[node], end = off[node + 1];
    const float di = dinv_in[node];
    const float4* y4 = (const float4*)y;

    for (int c = lane; c < Kpad4; c += 32) {
        float4 acc = make_float4(0.f, 0.f, 0.f, 0.f);
        if (c < K4) {
            for (int j = beg; j < end; j++) {
                const int s = csc[j];
                float4 v = y4[(size_t)s * K4 + c];
                const float sc = dout ? dout[s] : 1.0f;
                acc.x += v.x * sc; acc.y += v.y * sc; acc.z += v.z * sc; acc.w += v.w * sc;
            }
        }
        const uint32_t h0 = pack2h(acc.x * di, acc.y * di);
        const uint32_t h1 = pack2h(acc.z * di, acc.w * di);
        *reinterpret_cast<uint2*>(A + (size_t)node * sNext + c * 4) = make_uint2(h0, h1);
    }
}

// ================= gather_post =================
__global__ __launch_bounds__(256)
void gather_post(const float* __restrict__ t, const int* __restrict__ off,
                 const int* __restrict__ csc, int N4, int cpn,
                 __half* __restrict__ A, int sNext,
                 const float* __restrict__ bias, const float* __restrict__ dinv_in,
                 const float* __restrict__ dinv_out, float* __restrict__ outF) {
    const int gw = blockIdx.x * 8 + (threadIdx.x >> 5);
    const int lane = threadIdx.x & 31;
    const int node = gw / cpn, chunk = gw - node * cpn;
    if (node >= N_NODES) return;
    const int c = chunk * 32 + lane;

    const float4* t4 = (const float4*)t;
    const int beg = off[node], end = off[node + 1];
    float4 acc = make_float4(0.f, 0.f, 0.f, 0.f);
    for (int j = beg; j < end; j++) {
        const int s = csc[j];
        float4 v = t4[(size_t)s * N4 + c];
        acc.x += v.x; acc.y += v.y; acc.z += v.z; acc.w += v.w;
    }
    const float di = dinv_in[node];
    const float dv = dinv_out[node];
    const float4 b = ((const float4*)bias)[c];
    float v0 = fmaf(acc.x, di, b.x);
    float v1 = fmaf(acc.y, di, b.y);
    float v2 = fmaf(acc.z, di, b.z);
    float v3 = fmaf(acc.w, di, b.w);
    v0 = ((v0 < 0.f) ? 0.01f * v0 : v0) * dv;
    v1 = ((v1 < 0.f) ? 0.01f * v1 : v1) * dv;
    v2 = ((v2 < 0.f) ? 0.01f * v2 : v2) * dv;
    v3 = ((v3 < 0.f) ? 0.01f * v3 : v3) * dv;

    if (outF) {
        ((float4*)outF)[(size_t)node * N4 + c] = make_float4(v0, v1, v2, v3);
    } else {
        const uint32_t h0 = pack2h(v0, v1);
        const uint32_t h1 = pack2h(v2, v3);
        *reinterpret_cast<uint2*>(A + (size_t)node * sNext + c * 4) = make_uint2(h0, h1);
    }
}

// ================= launch =================
extern "C" void kernel_launch(void* const* d_in, const int* in_sizes, int n_in,
                              void* d_out, int out_size) {
    const float* x = (const float*)d_in[0];
    const int* ei = (const int*)d_in[1];   // int32 (JAX x64 disabled)
    const float* W[5] = {(const float*)d_in[2], (const float*)d_in[4], (const float*)d_in[6],
                         (const float*)d_in[8], (const float*)d_in[10]};
    const float* B[5] = {(const float*)d_in[3], (const float*)d_in[5], (const float*)d_in[7],
                         (const float*)d_in[9], (const float*)d_in[11]};

    const int M = N_NODES;
    const int nE = N_EDGES;
    const int* src = ei;
    const int* dstp = ei + nE;

    float *tP, *yP, *doutP, *dinP;
    __half *A0, *A1, *WfP;
    int *idegP, *odegP, *offP, *curP, *cscP, *bsumP;
    cudaGetSymbolAddress((void**)&tP, g_t);
    cudaGetSymbolAddress((void**)&yP, g_y);
    cudaGetSymbolAddress((void**)&A0, g_A0);
    cudaGetSymbolAddress((void**)&A1, g_A1);
    cudaGetSymbolAddress((void**)&WfP, g_Wf);
    cudaGetSymbolAddress((void**)&doutP, g_dinv_out);
    cudaGetSymbolAddress((void**)&dinP, g_dinv_in);
    cudaGetSymbolAddress((void**)&idegP, g_ideg);
    cudaGetSymbolAddress((void**)&odegP, g_odeg);
    cudaGetSymbolAddress((void**)&offP, g_off);
    cudaGetSymbolAddress((void**)&curP, g_cur);
    cudaGetSymbolAddress((void**)&cscP, g_csc);
    cudaGetSymbolAddress((void**)&bsumP, g_bsum);

    cudaFuncSetAttribute(gemm_mma, cudaFuncAttributeMaxDynamicSharedMemorySize, SMEM_TOTAL_B);

    // degrees + parallel scan + CSC fill
    hist_kernel<<<(nE + 255) / 256, 256>>>(src, dstp, odegP, idegP, nE);
    blocksum_kernel<<<SCAN_NB, SCAN_BS>>>(idegP, bsumP);
    scanpart_kernel<<<1, 256>>>(bsumP, SCAN_NB);
    offsets_dinv_kernel<<<SCAN_NB, SCAN_BS>>>(idegP, odegP, bsumP, offP, curP, doutP, dinP);
    fill_kernel<<<(nE + 255) / 256, 256>>>(src, dstp, curP, cscP, nE);
    // layer-1 pre-aggregation (K=300 -> fp16 A0, stride 320)
    gather_pre<<<(M + 7) / 8, 256>>>(x, doutP, offP, cscP, 75, 80, A0, 320, dinP);
    // all weight planes
    prep_w_all<<<640, 256>>>(W[0], W[1], W[2], W[3], W[4], WfP);

    // Layer 1 GEMM (K=320, N=1024) epilogue -> fp16 A1
    {
        dim3 grid(1024 / 128, M_PAD / 128);
        gemm_mma<<<grid, 256, SMEM_TOTAL_B>>>(A0, WfP + WOFF0, nullptr,
                                              M, 1024, 320, 1, B[0], doutP, A1, 1024);
    }
    // Layer 2 (K=1024, N=512)
    {
        dim3 grid(512 / 128, M_PAD / 128);
        gemm_mma<<<grid, 256, SMEM_TOTAL_B>>>(A1, WfP + WOFF1, tP,
                                              M, 512, 1024, 0, nullptr, nullptr, nullptr, 0);
    }
    gather_post<<<(M * 4 + 7) / 8, 256>>>(tP, offP, cscP, 128, 4, A0, 512,
                                          B[1], dinP, doutP, nullptr);
    // Layer 3 (K=512, N=256)
    {
        dim3 grid(256 / 128, M_PAD / 128);
        gemm_mma<<<grid, 256, SMEM_TOTAL_B>>>(A0, WfP + WOFF2, tP,
                                              M, 256, 512, 0, nullptr, nullptr, nullptr, 0);
    }
    gather_post<<<(M * 2 + 7) / 8, 256>>>(tP, offP, cscP, 64, 2, A1, 256,
                                          B[2], dinP, doutP, nullptr);
    // Layer 4 (K=256, N=128) -> fp32 y
    {
        dim3 grid(128 / 128, M_PAD / 128);
        gemm_mma<<<grid, 256, SMEM_TOTAL_B>>>(A1, WfP + WOFF3, tP,
                                              M, 128, 256, 0, nullptr, nullptr, nullptr, 0);
    }
    gather_post<<<(M + 7) / 8, 256>>>(tP, offP, cscP, 32, 1, nullptr, 0,
                                      B[3], dinP, doutP, yP);
    // Layer 5 (aggregate-first, K=128, N=2048) -> d_out
    gather_pre<<<(M + 7) / 8, 256>>>(yP, nullptr, offP, cscP, 32, 32, A0, 128, dinP);
    {
        dim3 grid(2048 / 128, M_PAD / 128);
        gemm_mma<<<grid, 256, SMEM_TOTAL_B>>>(A0, WfP + WOFF4, (float*)d_out,
                                              M, 2048, 128, 2, B[4], nullptr, nullptr, 0);
    }
    // restore degree arrays for next replay
    cleanup_kernel<<<(M + 255) / 256, 256>>>(idegP, odegP);
}

// round 16
// speedup vs baseline: 2.2429x; 1.0320x over previous
#include <cuda_runtime.h>
#include <cuda_bf16.h>
#include <cuda_fp16.h>
#include <cstdint>

// ---------------- problem constants ----------------
#define N_NODES 50000
#define N_EDGES 250000
#define M_PAD 50048           // 391 * 128
// dims: 300 -> 1024 -> 512 -> 256 -> 128 -> 2048

// ---------------- static device scratch ----------------
// __device__ globals load zeroed; g_ideg/g_odeg are re-zeroed at the END of
// each replay (cleanup_kernel) so every graph replay starts from zero.
__device__ __align__(256) __half g_t[(size_t)N_NODES * 512];            // GEMM fp16 out (layers 2-4)
__device__ __align__(256) __half g_y[(size_t)N_NODES * 128];            // layer-4 activation fp16
__device__ __align__(256) __half g_A0[(size_t)M_PAD * 1024];            // fp16 A ping
__device__ __align__(256) __half g_A1[(size_t)M_PAD * 1024];            // fp16 A pong
__device__ __align__(256) __half g_Wf[1277952];                         // all layers, fp16 W plane
__device__ __align__(256) float g_dinv_out[N_NODES];
__device__ __align__(256) float g_dinv_in[N_NODES];
// CSC structures
__device__ __align__(256) int g_ideg[N_NODES];   // zero at entry
__device__ __align__(256) int g_odeg[N_NODES];   // zero at entry
__device__ __align__(256) int g_off[N_NODES + 4];
__device__ __align__(256) int g_cur[N_NODES];
__device__ __align__(256) int g_csc[N_EDGES];
__device__ __align__(256) int g_bsum[128];

// per-layer W plane offsets (fp16 elements)
#define WOFF0 0
#define WOFF1 327680
#define WOFF2 851968
#define WOFF3 983040
#define WOFF4 1015808

// ================= helpers =================
__device__ __forceinline__ uint32_t smem_u32(const void* p) {
    uint32_t a;
    asm("{ .reg .u64 t; cvta.to.shared.u64 t, %1; cvt.u32.u64 %0, t; }" : "=r"(a) : "l"(p));
    return a;
}

__device__ __forceinline__ void ldm_x4(uint32_t& r0, uint32_t& r1, uint32_t& r2, uint32_t& r3,
                                       uint32_t addr) {
    asm volatile("ldmatrix.sync.aligned.m8n8.x4.shared.b16 {%0,%1,%2,%3}, [%4];"
                 : "=r"(r0), "=r"(r1), "=r"(r2), "=r"(r3) : "r"(addr));
}

__device__ __forceinline__ void mma_f16(float* d, const uint32_t* a, const uint32_t* b) {
    asm volatile("mma.sync.aligned.m16n8k16.row.col.f32.f16.f16.f32 "
                 "{%0,%1,%2,%3}, {%4,%5,%6,%7}, {%8,%9}, {%0,%1,%2,%3};"
                 : "+f"(d[0]), "+f"(d[1]), "+f"(d[2]), "+f"(d[3])
                 : "r"(a[0]), "r"(a[1]), "r"(a[2]), "r"(a[3]), "r"(b[0]), "r"(b[1]));
}

// fp32 pair -> packed fp16 pair (low 16 bits = first element)
__device__ __forceinline__ uint32_t pack2h(float a, float b) {
    __half ah = __float2half_rn(a);
    __half bh = __float2half_rn(b);
    return ((uint32_t)__half_as_ushort(bh) << 16) | (uint32_t)__half_as_ushort(ah);
}

// unpack u32 (2 halves) -> float2
__device__ __forceinline__ float2 unpack2h(uint32_t u) {
    __half2 h = *reinterpret_cast<__half2*>(&u);
    return __half22float2(h);
}

// ================= pipelined fp16 mma.sync GEMM (128x128, 2-stage) =================
// C = A @ Wf^T.  A fp16 [M_PAD, sA], Wf fp16 [N, sA] (k-major rows), fp32 accum.
// Single __syncthreads per k-tile.
// Epilogue modes:
//  0: t[m][n]  = fp16(d)                  (packed fp16, stride sNext=N -> oA)
//  1: A'(next) = fp16(leaky(d + bias[n]) * dout[m])   (stride sNext -> oA)
//  2: C[m][n]  = d + bias[n]              (final fp32 output)
#define APAD 40                 // fp16 row stride in smem (80B)
#define TILE_B 10240            // 128*40*2 bytes per tile
#define STAGE_B 20480           // 2 tiles (A, Wf)
#define SMEM_TOTAL_B 40960      // 2 stages

__global__ __launch_bounds__(256)
void gemm_mma(const __half* __restrict__ A, const __half* __restrict__ Wf,
              float* __restrict__ C, int M, int N, int sA,
              int mode, const float* __restrict__ bias, const float* __restrict__ dout,
              __half* __restrict__ oA, int sNext) {
    extern __shared__ __half dsm[];
    const uint32_t sbase = smem_u32(dsm);

    const int tid = threadIdx.x, lane = tid & 31, wid = tid >> 5;
    const int bm = blockIdx.y * 128, bn = blockIdx.x * 128;
    const int wm = (wid >> 1) * 32, wn = (wid & 1) * 64;
    const int nkt = sA >> 5;

    const int g = lane >> 3, l8 = lane & 7;
    const uint32_t aoff = (uint32_t)(((g & 1) * 8 + l8) * APAD + (g >> 1) * 8);
    const uint32_t boff = (uint32_t)(((g >> 1) * 8 + l8) * APAD + (g & 1) * 8);

    auto load_stage = [&](int kt, int st) {
        const int k0 = kt << 5;
        #pragma unroll
        for (int it = 0; it < 4; it++) {
            const int idx = it * 256 + tid;
            const int t = idx >> 9, rc = idx & 511;
            const int r = rc >> 2, c = rc & 3;
            const __half* gsrc = (t == 0) ? A + (size_t)(bm + r) * sA + k0 + c * 8
                                          : Wf + (size_t)(bn + r) * sA + k0 + c * 8;
            const uint32_t d = sbase + st * STAGE_B + t * TILE_B + r * 80 + c * 16;
            asm volatile("cp.async.ca.shared.global [%0], [%1], 16;" :: "r"(d), "l"(gsrc));
        }
    };

    float acc[2][8][4] = {};

    load_stage(0, 0);
    asm volatile("cp.async.commit_group;" ::: "memory");

    for (int kt = 0; kt < nkt; kt++) {
        const int st = kt & 1;

        asm volatile("cp.async.wait_group 0;" ::: "memory");   // stage kt arrived
        __syncthreads();                                        // + buf st^1 readers done

        if (kt + 1 < nkt) {
            load_stage(kt + 1, st ^ 1);
            asm volatile("cp.async.commit_group;" ::: "memory");
        }

        const uint32_t sA_u = sbase + st * STAGE_B;
        const uint32_t sW_u = sA_u + TILE_B;

        #pragma unroll
        for (int ks = 0; ks < 2; ks++) {
            uint32_t ar[2][4];
            #pragma unroll
            for (int mb = 0; mb < 2; mb++) {
                const uint32_t off = (aoff + (uint32_t)(wm + mb * 16) * APAD + ks * 16) * 2;
                ldm_x4(ar[mb][0], ar[mb][1], ar[mb][2], ar[mb][3], sA_u + off);
            }
            #pragma unroll
            for (int nbp = 0; nbp < 4; nbp++) {
                const uint32_t off = (boff + (uint32_t)(wn + nbp * 16) * APAD + ks * 16) * 2;
                uint32_t wf[4];
                ldm_x4(wf[0], wf[1], wf[2], wf[3], sW_u + off);
                #pragma unroll
                for (int h = 0; h < 2; h++) {
                    #pragma unroll
                    for (int mb = 0; mb < 2; mb++) {
                        mma_f16(acc[mb][nbp * 2 + h], ar[mb], wf + h * 2);
                    }
                }
            }
        }
    }

    const int mrow = lane >> 2, ncol = (lane & 3) * 2;
    #pragma unroll
    for (int mb = 0; mb < 2; mb++) {
        const int m0 = bm + wm + mb * 16 + mrow;
        float dv0 = 0.f, dv1 = 0.f;
        if (mode == 1) {
            if (m0 < M) dv0 = dout[m0];
            if (m0 + 8 < M) dv1 = dout[m0 + 8];
        }
        #pragma unroll
        for (int nb = 0; nb < 8; nb++) {
            const float* d = acc[mb][nb];
            const int n = bn + wn + nb * 8 + ncol;
            if (mode == 0) {
                if (m0 < M)
                    *reinterpret_cast<uint32_t*>(oA + (size_t)m0 * sNext + n) = pack2h(d[0], d[1]);
                if (m0 + 8 < M)
                    *reinterpret_cast<uint32_t*>(oA + (size_t)(m0 + 8) * sNext + n) = pack2h(d[2], d[3]);
            } else if (mode == 2) {
                const float b0 = bias[n], b1 = bias[n + 1];
                if (m0 < M)
                    *reinterpret_cast<float2*>(C + (size_t)m0 * N + n) = make_float2(d[0] + b0, d[1] + b1);
                if (m0 + 8 < M)
                    *reinterpret_cast<float2*>(C + (size_t)(m0 + 8) * N + n) = make_float2(d[2] + b0, d[3] + b1);
            } else {
                const float b0 = bias[n], b1 = bias[n + 1];
                if (m0 < M) {
                    float v0 = d[0] + b0, v1 = d[1] + b1;
                    v0 = ((v0 < 0.f) ? 0.01f * v0 : v0) * dv0;
                    v1 = ((v1 < 0.f) ? 0.01f * v1 : v1) * dv0;
                    *reinterpret_cast<uint32_t*>(oA + (size_t)m0 * sNext + n) = pack2h(v0, v1);
                }
                if (m0 + 8 < M) {
                    float v0 = d[2] + b0, v1 = d[3] + b1;
                    v0 = ((v0 < 0.f) ? 0.01f * v0 : v0) * dv1;
                    v1 = ((v1 < 0.f) ? 0.01f * v1 : v1) * dv1;
                    *reinterpret_cast<uint32_t*>(oA + (size_t)(m0 + 8) * sNext + n) = pack2h(v0, v1);
                }
            }
        }
    }
}

// ================= fused W prep: all 5 layers, single fp16 plane =================
__global__ void prep_w_all(const float* __restrict__ W0, const float* __restrict__ W1,
                           const float* __restrict__ W2, const float* __restrict__ W3,
                           const float* __restrict__ W4,
                           __half* __restrict__ Wf) {
    const int starts[6] = {0, 163840, 425984, 491520, 507904, 638976};
    const int Ks[5]     = {300, 1024, 512, 256, 128};
    const int Ns[5]     = {1024, 512, 256, 128, 2048};
    const int Kpads[5]  = {320, 1024, 512, 256, 128};
    const int woffs[5]  = {WOFF0, WOFF1, WOFF2, WOFF3, WOFF4};
    const float* Ws[5]  = {W0, W1, W2, W3, W4};

    int idx = blockIdx.x * blockDim.x + threadIdx.x;
    int stride = gridDim.x * blockDim.x;
    for (; idx < 638976; idx += stride) {
        int l = 0;
        #pragma unroll
        for (int q = 1; q < 5; q++) if (idx >= starts[q]) l = q;
        const int p = idx - starts[l];
        const int Kp2 = Kpads[l] >> 1;
        const int n = p / Kp2, pk = p - n * Kp2;
        const int k = pk * 2;
        const int K = Ks[l], N = Ns[l];
        float w0 = 0.f, w1 = 0.f;
        if (k < K)     w0 = Ws[l][(size_t)k * N + n];
        if (k + 1 < K) w1 = Ws[l][(size_t)(k + 1) * N + n];
        ((uint32_t*)(Wf + woffs[l]))[p] = pack2h(w0, w1);
    }
}

// ================= CSC build (parallel scan) =================
__global__ void hist_kernel(const int* __restrict__ src, const int* __restrict__ dst,
                            int* __restrict__ odeg, int* __restrict__ ideg, int nE) {
    int e = blockIdx.x * blockDim.x + threadIdx.x;
    if (e >= nE) return;
    int s = src[e], d = dst[e];
    if ((unsigned)s < N_NODES) atomicAdd(&odeg[s], 1);
    if ((unsigned)d < N_NODES) atomicAdd(&ideg[d], 1);
}

#define SCAN_BS 512
#define SCAN_NB ((N_NODES + SCAN_BS - 1) / SCAN_BS)  // 98

__global__ void blocksum_kernel(const int* __restrict__ deg, int* __restrict__ bsum) {
    __shared__ int sh[SCAN_BS];
    int i = blockIdx.x * SCAN_BS + threadIdx.x;
    sh[threadIdx.x] = (i < N_NODES) ? deg[i] : 0;
    __syncthreads();
    for (int s = SCAN_BS / 2; s > 0; s >>= 1) {
        if (threadIdx.x < s) sh[threadIdx.x] += sh[threadIdx.x + s];
        __syncthreads();
    }
    if (threadIdx.x == 0) bsum[blockIdx.x] = sh[0];
}

__global__ void scanpart_kernel(int* __restrict__ bsum, int nb) {
    __shared__ int sh[256];
    int t = threadIdx.x;
    int v = (t < nb) ? bsum[t] : 0;
    sh[t] = v;
    __syncthreads();
    for (int s = 1; s < 256; s <<= 1) {
        int add = (t >= s) ? sh[t - s] : 0;
        __syncthreads();
        sh[t] += add;
        __syncthreads();
    }
    if (t < nb) bsum[t] = sh[t] - v;  // exclusive
}

__global__ void offsets_dinv_kernel(const int* __restrict__ ideg, const int* __restrict__ odeg,
                                    const int* __restrict__ bsum,
                                    int* __restrict__ off, int* __restrict__ cur,
                                    float* __restrict__ dout, float* __restrict__ din) {
    __shared__ int sh[SCAN_BS];
    int t = threadIdx.x;
    int i = blockIdx.x * SCAN_BS + t;
    int v = (i < N_NODES) ? ideg[i] : 0;
    if (i < N_NODES) {
        dout[i] = rsqrtf(fmaxf((float)odeg[i], 1.0f));
        din[i]  = rsqrtf(fmaxf((float)v, 1.0f));
    }
    sh[t] = v;
    __syncthreads();
    for (int s = 1; s < SCAN_BS; s <<= 1) {
        int add = (t >= s) ? sh[t - s] : 0;
        __syncthreads();
        sh[t] += add;
        __syncthreads();
    }
    if (i < N_NODES) {
        int excl = sh[t] - v + bsum[blockIdx.x];
        off[i] = excl;
        cur[i] = excl;
        if (i == N_NODES - 1) off[N_NODES] = excl + v;
    }
}

__global__ void fill_kernel(const int* __restrict__ src, const int* __restrict__ dst,
                            int* __restrict__ cur, int* __restrict__ csc, int nE) {
    int e = blockIdx.x * blockDim.x + threadIdx.x;
    if (e >= nE) return;
    int s = src[e], d = dst[e];
    if ((unsigned)s >= N_NODES || (unsigned)d >= N_NODES) return;
    int pos = atomicAdd(&cur[d], 1);
    csc[pos] = s;
}

__global__ void cleanup_kernel(int* __restrict__ ideg, int* __restrict__ odeg) {
    int i = blockIdx.x * blockDim.x + threadIdx.x;
    if (i < N_NODES) { ideg[i] = 0; odeg[i] = 0; }
}

// ================= gather_pre (fp32 input x): u = dinv_in ⊙ S (dout ⊙) x -> fp16 =================
__global__ __launch_bounds__(256)
void gather_pre(const float* __restrict__ y, const float* __restrict__ dout,
                const int* __restrict__ off, const int* __restrict__ csc,
                int K4, int Kpad4,
                __half* __restrict__ A, int sNext,
                const float* __restrict__ dinv_in) {
    const int node = blockIdx.x * 8 + (threadIdx.x >> 5);
    if (node >= N_NODES) return;
    const int lane = threadIdx.x & 31;
    const int beg = off[node], end = off[node + 1];
    const float di = dinv_in[node];
    const float4* y4 = (const float4*)y;

    for (int c = lane; c < Kpad4; c += 32) {
        float4 acc = make_float4(0.f, 0.f, 0.f, 0.f);
        if (c < K4) {
            for (int j = beg; j < end; j++) {
                const int s = csc[j];
                float4 v = y4[(size_t)s * K4 + c];
                const float sc = dout ? dout[s] : 1.0f;
                acc.x += v.x * sc; acc.y += v.y * sc; acc.z += v.z * sc; acc.w += v.w * sc;
            }
        }
        const uint32_t h0 = pack2h(acc.x * di, acc.y * di);
        const uint32_t h1 = pack2h(acc.z * di, acc.w * di);
        *reinterpret_cast<uint2*>(A + (size_t)node * sNext + c * 4) = make_uint2(h0, h1);
    }
}

// ================= gather_pre_h (fp16 input y, layer 5): u = dinv_in ⊙ S y -> fp16 =================
__global__ __launch_bounds__(256)
void gather_pre_h(const __half* __restrict__ y, const int* __restrict__ off,
                  const int* __restrict__ csc, int K8,
                  __half* __restrict__ A, int sNext,
                  const float* __restrict__ dinv_in) {
    const int node = blockIdx.x * 8 + (threadIdx.x >> 5);
    if (node >= N_NODES) return;
    const int lane = threadIdx.x & 31;
    if (lane >= K8) return;
    const int beg = off[node], end = off[node + 1];
    const float di = dinv_in[node];
    const uint4* y8 = (const uint4*)y;
    const int c = lane;

    float acc[8] = {};
    for (int j = beg; j < end; j++) {
        const int s = csc[j];
        uint4 v = y8[(size_t)s * K8 + c];
        float2 f0 = unpack2h(v.x), f1 = unpack2h(v.y), f2 = unpack2h(v.z), f3 = unpack2h(v.w);
        acc[0] += f0.x; acc[1] += f0.y; acc[2] += f1.x; acc[3] += f1.y;
        acc[4] += f2.x; acc[5] += f2.y; acc[6] += f3.x; acc[7] += f3.y;
    }
    uint4 o;
    o.x = pack2h(acc[0] * di, acc[1] * di);
    o.y = pack2h(acc[2] * di, acc[3] * di);
    o.z = pack2h(acc[4] * di, acc[5] * di);
    o.w = pack2h(acc[6] * di, acc[7] * di);
    *reinterpret_cast<uint4*>(A + (size_t)node * sNext + c * 8) = o;
}

// ================= gather_post: agg = S t (fp16 rows, fp32 accum) =================
// act = leaky(dinv_in*agg + bias) * dinv_out -> fp16 A(next) or fp16 y (outY)
__global__ __launch_bounds__(256)
void gather_post(const __half* __restrict__ t, const int* __restrict__ off,
                 const int* __restrict__ csc, int N8, int cpn,
                 __half* __restrict__ A, int sNext,
                 const float* __restrict__ bias, const float* __restrict__ dinv_in,
                 const float* __restrict__ dinv_out, __half* __restrict__ outY, int sY) {
    const int gw = blockIdx.x * 8 + (threadIdx.x >> 5);
    const int lane = threadIdx.x & 31;
    const int node = gw / cpn, chunk = gw - node * cpn;
    if (node >= N_NODES) return;
    const int c = chunk * 32 + lane;
    if (c >= N8) return;

    const uint4* t8 = (const uint4*)t;
    const int beg = off[node], end = off[node + 1];
    float acc[8] = {};
    for (int j = beg; j < end; j++) {
        const int s = csc[j];
        uint4 v = t8[(size_t)s * N8 + c];
        float2 f0 = unpack2h(v.x), f1 = unpack2h(v.y), f2 = unpack2h(v.z), f3 = unpack2h(v.w);
        acc[0] += f0.x; acc[1] += f0.y; acc[2] += f1.x; acc[3] += f1.y;
        acc[4] += f2.x; acc[5] += f2.y; acc[6] += f3.x; acc[7] += f3.y;
    }
    const float di = dinv_in[node];
    const float dv = dinv_out[node];
    float v[8];
    #pragma unroll
    for (int i = 0; i < 8; i++) {
        float u = fmaf(acc[i], di, bias[c * 8 + i]);
        v[i] = ((u < 0.f) ? 0.01f * u : u) * dv;
    }
    uint4 o;
    o.x = pack2h(v[0], v[1]);
    o.y = pack2h(v[2], v[3]);
    o.z = pack2h(v[4], v[5]);
    o.w = pack2h(v[6], v[7]);
    if (outY)
        *reinterpret_cast<uint4*>(outY + (size_t)node * sY + c * 8) = o;
    else
        *reinterpret_cast<uint4*>(A + (size_t)node * sNext + c * 8) = o;
}

// ================= launch =================
extern "C" void kernel_launch(void* const* d_in, const int* in_sizes, int n_in,
                              void* d_out, int out_size) {
    const float* x = (const float*)d_in[0];
    const int* ei = (const int*)d_in[1];   // int32 (JAX x64 disabled)
    const float* W[5] = {(const float*)d_in[2], (const float*)d_in[4], (const float*)d_in[6],
                         (const float*)d_in[8], (const float*)d_in[10]};
    const float* B[5] = {(const float*)d_in[3], (const float*)d_in[5], (const float*)d_in[7],
                         (const float*)d_in[9], (const float*)d_in[11]};

    const int M = N_NODES;
    const int nE = N_EDGES;
    const int* src = ei;
    const int* dstp = ei + nE;

    float *doutP, *dinP;
    __half *tP, *yP, *A0, *A1, *WfP;
    int *idegP, *odegP, *offP, *curP, *cscP, *bsumP;
    cudaGetSymbolAddress((void**)&tP, g_t);
    cudaGetSymbolAddress((void**)&yP, g_y);
    cudaGetSymbolAddress((void**)&A0, g_A0);
    cudaGetSymbolAddress((void**)&A1, g_A1);
    cudaGetSymbolAddress((void**)&WfP, g_Wf);
    cudaGetSymbolAddress((void**)&doutP, g_dinv_out);
    cudaGetSymbolAddress((void**)&dinP, g_dinv_in);
    cudaGetSymbolAddress((void**)&idegP, g_ideg);
    cudaGetSymbolAddress((void**)&odegP, g_odeg);
    cudaGetSymbolAddress((void**)&offP, g_off);
    cudaGetSymbolAddress((void**)&curP, g_cur);
    cudaGetSymbolAddress((void**)&cscP, g_csc);
    cudaGetSymbolAddress((void**)&bsumP, g_bsum);

    cudaFuncSetAttribute(gemm_mma, cudaFuncAttributeMaxDynamicSharedMemorySize, SMEM_TOTAL_B);

    // degrees + parallel scan + CSC fill
    hist_kernel<<<(nE + 255) / 256, 256>>>(src, dstp, odegP, idegP, nE);
    blocksum_kernel<<<SCAN_NB, SCAN_BS>>>(idegP, bsumP);
    scanpart_kernel<<<1, 256>>>(bsumP, SCAN_NB);
    offsets_dinv_kernel<<<SCAN_NB, SCAN_BS>>>(idegP, odegP, bsumP, offP, curP, doutP, dinP);
    fill_kernel<<<(nE + 255) / 256, 256>>>(src, dstp, curP, cscP, nE);
    // layer-1 pre-aggregation (fp32 x, K=300 -> fp16 A0, stride 320)
    gather_pre<<<(M + 7) / 8, 256>>>(x, doutP, offP, cscP, 75, 80, A0, 320, dinP);
    // all weight planes
    prep_w_all<<<640, 256>>>(W[0], W[1], W[2], W[3], W[4], WfP);

    // Layer 1 GEMM (K=320, N=1024) epilogue -> fp16 A1
    {
        dim3 grid(1024 / 128, M_PAD / 128);
        gemm_mma<<<grid, 256, SMEM_TOTAL_B>>>(A0, WfP + WOFF0, nullptr,
                                              M, 1024, 320, 1, B[0], doutP, A1, 1024);
    }
    // Layer 2 (K=1024, N=512) -> fp16 t
    {
        dim3 grid(512 / 128, M_PAD / 128);
        gemm_mma<<<grid, 256, SMEM_TOTAL_B>>>(A1, WfP + WOFF1, nullptr,
                                              M, 512, 1024, 0, nullptr, nullptr, tP, 512);
    }
    gather_post<<<(M * 2 + 7) / 8, 256>>>(tP, offP, cscP, 64, 2, A0, 512,
                                          B[1], dinP, doutP, nullptr, 0);
    // Layer 3 (K=512, N=256) -> fp16 t
    {
        dim3 grid(256 / 128, M_PAD / 128);
        gemm_mma<<<grid, 256, SMEM_TOTAL_B>>>(A0, WfP + WOFF2, nullptr,
                                              M, 256, 512, 0, nullptr, nullptr, tP, 256);
    }
    gather_post<<<(M + 7) / 8, 256>>>(tP, offP, cscP, 32, 1, A1, 256,
                                      B[2], dinP, doutP, nullptr, 0);
    // Layer 4 (K=256, N=128) -> fp16 t -> fp16 y
    {
        dim3 grid(128 / 128, M_PAD / 128);
        gemm_mma<<<grid, 256, SMEM_TOTAL_B>>>(A1, WfP + WOFF3, nullptr,
                                              M, 128, 256, 0, nullptr, nullptr, tP, 128);
    }
    gather_post<<<(M + 7) / 8, 256>>>(tP, offP, cscP, 16, 1, nullptr, 0,
                                      B[3], dinP, doutP, yP, 128);
    // Layer 5 (aggregate-first, fp16 y, K=128, N=2048) -> d_out
    gather_pre_h<<<(M + 7) / 8, 256>>>(yP, offP, cscP, 16, A0, 128, dinP);
    {
        dim3 grid(2048 / 128, M_PAD / 128);
        gemm_mma<<<grid, 256, SMEM_TOTAL_B>>>(A0, WfP + WOFF4, (float*)d_out,
                                              M, 2048, 128, 2, B[4], nullptr, nullptr, 0);
    }
    // restore degree arrays for next replay
    cleanup_kernel<<<(M + 255) / 256, 256>>>(idegP, odegP);
}

// round 17
// speedup vs baseline: 2.5904x; 1.1550x over previous
#include <cuda_runtime.h>
#include <cuda_bf16.h>
#include <cuda_fp16.h>
#include <cstdint>

// ---------------- problem constants ----------------
#define N_NODES 50000
#define N_EDGES 250000
#define M_PAD 50048           // 391 * 128
// dims: 300 -> 1024 -> 512 -> 256 -> 128 -> 2048

// ---------------- static device scratch ----------------
// __device__ globals load zeroed; g_ideg/g_odeg are re-zeroed at the END of
// each replay (cleanup_kernel) so every graph replay starts from zero.
__device__ __align__(256) __half g_t[(size_t)N_NODES * 512];            // GEMM fp16 out (layers 2-4)
__device__ __align__(256) __half g_y[(size_t)N_NODES * 128];            // layer-4 activation fp16
__device__ __align__(256) __half g_A0[(size_t)M_PAD * 1024];            // fp16 A ping
__device__ __align__(256) __half g_A1[(size_t)M_PAD * 1024];            // fp16 A pong
__device__ __align__(256) __half g_Wf[1277952];                         // all layers, fp16 W plane
__device__ __align__(256) float g_dinv_out[N_NODES];
__device__ __align__(256) float g_dinv_in[N_NODES];
// CSC structures
__device__ __align__(256) int g_ideg[N_NODES];   // zero at entry
__device__ __align__(256) int g_odeg[N_NODES];   // zero at entry
__device__ __align__(256) int g_off[N_NODES + 4];
__device__ __align__(256) int g_cur[N_NODES];
__device__ __align__(256) int g_csc[N_EDGES];
__device__ __align__(256) int g_bsum[128];

// per-layer W plane offsets (fp16 elements)
#define WOFF0 0
#define WOFF1 327680
#define WOFF2 851968
#define WOFF3 983040
#define WOFF4 1015808

// ================= helpers =================
__device__ __forceinline__ uint32_t smem_u32(const void* p) {
    uint32_t a;
    asm("{ .reg .u64 t; cvta.to.shared.u64 t, %1; cvt.u32.u64 %0, t; }" : "=r"(a) : "l"(p));
    return a;
}

__device__ __forceinline__ void ldm_x4(uint32_t& r0, uint32_t& r1, uint32_t& r2, uint32_t& r3,
                                       uint32_t addr) {
    asm volatile("ldmatrix.sync.aligned.m8n8.x4.shared.b16 {%0,%1,%2,%3}, [%4];"
                 : "=r"(r0), "=r"(r1), "=r"(r2), "=r"(r3) : "r"(addr));
}

__device__ __forceinline__ void mma_f16(float* d, const uint32_t* a, const uint32_t* b) {
    asm volatile("mma.sync.aligned.m16n8k16.row.col.f32.f16.f16.f32 "
                 "{%0,%1,%2,%3}, {%4,%5,%6,%7}, {%8,%9}, {%0,%1,%2,%3};"
                 : "+f"(d[0]), "+f"(d[1]), "+f"(d[2]), "+f"(d[3])
                 : "r"(a[0]), "r"(a[1]), "r"(a[2]), "r"(a[3]), "r"(b[0]), "r"(b[1]));
}

// fp32 pair -> packed fp16 pair (low 16 bits = first element)
__device__ __forceinline__ uint32_t pack2h(float a, float b) {
    __half ah = __float2half_rn(a);
    __half bh = __float2half_rn(b);
    return ((uint32_t)__half_as_ushort(bh) << 16) | (uint32_t)__half_as_ushort(ah);
}

// unpack u32 (2 halves) -> float2
__device__ __forceinline__ float2 unpack2h(uint32_t u) {
    __half2 h = *reinterpret_cast<__half2*>(&u);
    return __half22float2(h);
}

// ================= pipelined fp16 mma.sync GEMM (128x128, BK=64, 2-stage) =================
// C = A @ Wf^T.  A fp16 [M_PAD, sA], Wf fp16 [N, sA] (k-major rows), fp32 accum.
// Single __syncthreads per k-tile; BK=64 doubles the MMA stretch per stage so
// the next stage's cp.async latency is fully covered, and halves barrier count.
// Epilogue modes:
//  0: t[m][n]  = fp16(d)                  (packed fp16, stride sNext=N -> oA)
//  1: A'(next) = fp16(leaky(d + bias[n]) * dout[m])   (stride sNext -> oA)
//  2: C[m][n]  = d + bias[n]              (final fp32 output)
#define APAD 72                 // fp16 row stride in smem (144B); rows hit banks 0,4,..,28
#define TILE_B 18432            // 128*72*2 bytes per tile
#define STAGE_B 36864           // 2 tiles (A, Wf)
#define SMEM_TOTAL_B 73728      // 2 stages

__global__ __launch_bounds__(256)
void gemm_mma(const __half* __restrict__ A, const __half* __restrict__ Wf,
              float* __restrict__ C, int M, int N, int sA,
              int mode, const float* __restrict__ bias, const float* __restrict__ dout,
              __half* __restrict__ oA, int sNext) {
    extern __shared__ __half dsm[];
    const uint32_t sbase = smem_u32(dsm);

    const int tid = threadIdx.x, lane = tid & 31, wid = tid >> 5;
    const int bm = blockIdx.y * 128, bn = blockIdx.x * 128;
    const int wm = (wid >> 1) * 32, wn = (wid & 1) * 64;
    const int nkt = sA >> 6;           // k-tiles of 64

    const int g = lane >> 3, l8 = lane & 7;
    const uint32_t aoff = (uint32_t)(((g & 1) * 8 + l8) * APAD + (g >> 1) * 8);
    const uint32_t boff = (uint32_t)(((g >> 1) * 8 + l8) * APAD + (g & 1) * 8);

    // 2048 16B-chunks per stage (two 128x64 fp16 tiles) / 256 threads = 8 per thread
    auto load_stage = [&](int kt, int st) {
        const int k0 = kt << 6;
        #pragma unroll
        for (int it = 0; it < 8; it++) {
            const int idx = it * 256 + tid;
            const int t = idx >> 10, rc = idx & 1023;
            const int r = rc >> 3, c = rc & 7;
            const __half* gsrc = (t == 0) ? A + (size_t)(bm + r) * sA + k0 + c * 8
                                          : Wf + (size_t)(bn + r) * sA + k0 + c * 8;
            const uint32_t d = sbase + st * STAGE_B + t * TILE_B + r * 144 + c * 16;
            asm volatile("cp.async.ca.shared.global [%0], [%1], 16;" :: "r"(d), "l"(gsrc));
        }
    };

    float acc[2][8][4] = {};

    load_stage(0, 0);
    asm volatile("cp.async.commit_group;" ::: "memory");

    for (int kt = 0; kt < nkt; kt++) {
        const int st = kt & 1;

        asm volatile("cp.async.wait_group 0;" ::: "memory");   // stage kt arrived
        __syncthreads();                                        // + buf st^1 readers done

        if (kt + 1 < nkt) {
            load_stage(kt + 1, st ^ 1);
            asm volatile("cp.async.commit_group;" ::: "memory");
        }

        const uint32_t sA_u = sbase + st * STAGE_B;
        const uint32_t sW_u = sA_u + TILE_B;

        #pragma unroll
        for (int ks = 0; ks < 4; ks++) {
            uint32_t ar[2][4];
            #pragma unroll
            for (int mb = 0; mb < 2; mb++) {
                const uint32_t off = (aoff + (uint32_t)(wm + mb * 16) * APAD + ks * 16) * 2;
                ldm_x4(ar[mb][0], ar[mb][1], ar[mb][2], ar[mb][3], sA_u + off);
            }
            #pragma unroll
            for (int nbp = 0; nbp < 4; nbp++) {
                const uint32_t off = (boff + (uint32_t)(wn + nbp * 16) * APAD + ks * 16) * 2;
                uint32_t wf[4];
                ldm_x4(wf[0], wf[1], wf[2], wf[3], sW_u + off);
                #pragma unroll
                for (int h = 0; h < 2; h++) {
                    #pragma unroll
                    for (int mb = 0; mb < 2; mb++) {
                        mma_f16(acc[mb][nbp * 2 + h], ar[mb], wf + h * 2);
                    }
                }
            }
        }
    }

    const int mrow = lane >> 2, ncol = (lane & 3) * 2;
    #pragma unroll
    for (int mb = 0; mb < 2; mb++) {
        const int m0 = bm + wm + mb * 16 + mrow;
        float dv0 = 0.f, dv1 = 0.f;
        if (mode == 1) {
            if (m0 < M) dv0 = dout[m0];
            if (m0 + 8 < M) dv1 = dout[m0 + 8];
        }
        #pragma unroll
        for (int nb = 0; nb < 8; nb++) {
            const float* d = acc[mb][nb];
            const int n = bn + wn + nb * 8 + ncol;
            if (mode == 0) {
                if (m0 < M)
                    *reinterpret_cast<uint32_t*>(oA + (size_t)m0 * sNext + n) = pack2h(d[0], d[1]);
                if (m0 + 8 < M)
                    *reinterpret_cast<uint32_t*>(oA + (size_t)(m0 + 8) * sNext + n) = pack2h(d[2], d[3]);
            } else if (mode == 2) {
                const float b0 = bias[n], b1 = bias[n + 1];
                if (m0 < M)
                    *reinterpret_cast<float2*>(C + (size_t)m0 * N + n) = make_float2(d[0] + b0, d[1] + b1);
                if (m0 + 8 < M)
                    *reinterpret_cast<float2*>(C + (size_t)(m0 + 8) * N + n) = make_float2(d[2] + b0, d[3] + b1);
            } else {
                const float b0 = bias[n], b1 = bias[n + 1];
                if (m0 < M) {
                    float v0 = d[0] + b0, v1 = d[1] + b1;
                    v0 = ((v0 < 0.f) ? 0.01f * v0 : v0) * dv0;
                    v1 = ((v1 < 0.f) ? 0.01f * v1 : v1) * dv0;
                    *reinterpret_cast<uint32_t*>(oA + (size_t)m0 * sNext + n) = pack2h(v0, v1);
                }
                if (m0 + 8 < M) {
                    float v0 = d[2] + b0, v1 = d[3] + b1;
                    v0 = ((v0 < 0.f) ? 0.01f * v0 : v0) * dv1;
                    v1 = ((v1 < 0.f) ? 0.01f * v1 : v1) * dv1;
                    *reinterpret_cast<uint32_t*>(oA + (size_t)(m0 + 8) * sNext + n) = pack2h(v0, v1);
                }
            }
        }
    }
}

// ================= fused W prep: all 5 layers, single fp16 plane =================
__global__ void prep_w_all(const float* __restrict__ W0, const float* __restrict__ W1,
                           const float* __restrict__ W2, const float* __restrict__ W3,
                           const float* __restrict__ W4,
                           __half* __restrict__ Wf) {
    const int starts[6] = {0, 163840, 425984, 491520, 507904, 638976};
    const int Ks[5]     = {300, 1024, 512, 256, 128};
    const int Ns[5]     = {1024, 512, 256, 128, 2048};
    const int Kpads[5]  = {320, 1024, 512, 256, 128};
    const int woffs[5]  = {WOFF0, WOFF1, WOFF2, WOFF3, WOFF4};
    const float* Ws[5]  = {W0, W1, W2, W3, W4};

    int idx = blockIdx.x * blockDim.x + threadIdx.x;
    int stride = gridDim.x * blockDim.x;
    for (; idx < 638976; idx += stride) {
        int l = 0;
        #pragma unroll
        for (int q = 1; q < 5; q++) if (idx >= starts[q]) l = q;
        const int p = idx - starts[l];
        const int Kp2 = Kpads[l] >> 1;
        const int n = p / Kp2, pk = p - n * Kp2;
        const int k = pk * 2;
        const int K = Ks[l], N = Ns[l];
        float w0 = 0.f, w1 = 0.f;
        if (k < K)     w0 = Ws[l][(size_t)k * N + n];
        if (k + 1 < K) w1 = Ws[l][(size_t)(k + 1) * N + n];
        ((uint32_t*)(Wf + woffs[l]))[p] = pack2h(w0, w1);
    }
}

// ================= CSC build (parallel scan) =================
__global__ void hist_kernel(const int* __restrict__ src, const int* __restrict__ dst,
                            int* __restrict__ odeg, int* __restrict__ ideg, int nE) {
    int e = blockIdx.x * blockDim.x + threadIdx.x;
    if (e >= nE) return;
    int s = src[e], d = dst[e];
    if ((unsigned)s < N_NODES) atomicAdd(&odeg[s], 1);
    if ((unsigned)d < N_NODES) atomicAdd(&ideg[d], 1);
}

#define SCAN_BS 512
#define SCAN_NB ((N_NODES + SCAN_BS - 1) / SCAN_BS)  // 98

__global__ void blocksum_kernel(const int* __restrict__ deg, int* __restrict__ bsum) {
    __shared__ int sh[SCAN_BS];
    int i = blockIdx.x * SCAN_BS + threadIdx.x;
    sh[threadIdx.x] = (i < N_NODES) ? deg[i] : 0;
    __syncthreads();
    for (int s = SCAN_BS / 2; s > 0; s >>= 1) {
        if (threadIdx.x < s) sh[threadIdx.x] += sh[threadIdx.x + s];
        __syncthreads();
    }
    if (threadIdx.x == 0) bsum[blockIdx.x] = sh[0];
}

__global__ void scanpart_kernel(int* __restrict__ bsum, int nb) {
    __shared__ int sh[256];
    int t = threadIdx.x;
    int v = (t < nb) ? bsum[t] : 0;
    sh[t] = v;
    __syncthreads();
    for (int s = 1; s < 256; s <<= 1) {
        int add = (t >= s) ? sh[t - s] : 0;
        __syncthreads();
        sh[t] += add;
        __syncthreads();
    }
    if (t < nb) bsum[t] = sh[t] - v;  // exclusive
}

__global__ void offsets_dinv_kernel(const int* __restrict__ ideg, const int* __restrict__ odeg,
                                    const int* __restrict__ bsum,
                                    int* __restrict__ off, int* __restrict__ cur,
                                    float* __restrict__ dout, float* __restrict__ din) {
    __shared__ int sh[SCAN_BS];
    int t = threadIdx.x;
    int i = blockIdx.x * SCAN_BS + t;
    int v = (i < N_NODES) ? ideg[i] : 0;
    if (i < N_NODES) {
        dout[i] = rsqrtf(fmaxf((float)odeg[i], 1.0f));
        din[i]  = rsqrtf(fmaxf((float)v, 1.0f));
    }
    sh[t] = v;
    __syncthreads();
    for (int s = 1; s < SCAN_BS; s <<= 1) {
        int add = (t >= s) ? sh[t - s] : 0;
        __syncthreads();
        sh[t] += add;
        __syncthreads();
    }
    if (i < N_NODES) {
        int excl = sh[t] - v + bsum[blockIdx.x];
        off[i] = excl;
        cur[i] = excl;
        if (i == N_NODES - 1) off[N_NODES] = excl + v;
    }
}

__global__ void fill_kernel(const int* __restrict__ src, const int* __restrict__ dst,
                            int* __restrict__ cur, int* __restrict__ csc, int nE) {
    int e = blockIdx.x * blockDim.x + threadIdx.x;
    if (e >= nE) return;
    int s = src[e], d = dst[e];
    if ((unsigned)s >= N_NODES || (unsigned)d >= N_NODES) return;
    int pos = atomicAdd(&cur[d], 1);
    csc[pos] = s;
}

__global__ void cleanup_kernel(int* __restrict__ ideg, int* __restrict__ odeg) {
    int i = blockIdx.x * blockDim.x + threadIdx.x;
    if (i < N_NODES) { ideg[i] = 0; odeg[i] = 0; }
}

// ================= gather_pre (fp32 input x): u = dinv_in ⊙ S (dout ⊙) x -> fp16 =================
__global__ __launch_bounds__(256)
void gather_pre(const float* __restrict__ y, const float* __restrict__ dout,
                const int* __restrict__ off, const int* __restrict__ csc,
                int K4, int Kpad4,
                __half* __restrict__ A, int sNext,
                const float* __restrict__ dinv_in) {
    const int node = blockIdx.x * 8 + (threadIdx.x >> 5);
    if (node >= N_NODES) return;
    const int lane = threadIdx.x & 31;
    const int beg = off[node], end = off[node + 1];
    const float di = dinv_in[node];
    const float4* y4 = (const float4*)y;

    for (int c = lane; c < Kpad4; c += 32) {
        float4 acc = make_float4(0.f, 0.f, 0.f, 0.f);
        if (c < K4) {
            for (int j = beg; j < end; j++) {
                const int s = csc[j];
                float4 v = y4[(size_t)s * K4 + c];
                const float sc = dout ? dout[s] : 1.0f;
                acc.x += v.x * sc; acc.y += v.y * sc; acc.z += v.z * sc; acc.w += v.w * sc;
            }
        }
        const uint32_t h0 = pack2h(acc.x * di, acc.y * di);
        const uint32_t h1 = pack2h(acc.z * di, acc.w * di);
        *reinterpret_cast<uint2*>(A + (size_t)node * sNext + c * 4) = make_uint2(h0, h1);
    }
}

// ================= gather_pre_h (fp16 input y, layer 5): u = dinv_in ⊙ S y -> fp16 =================
__global__ __launch_bounds__(256)
void gather_pre_h(const __half* __restrict__ y, const int* __restrict__ off,
                  const int* __restrict__ csc, int K8,
                  __half* __restrict__ A, int sNext,
                  const float* __restrict__ dinv_in) {
    const int node = blockIdx.x * 8 + (threadIdx.x >> 5);
    if (node >= N_NODES) return;
    const int lane = threadIdx.x & 31;
    if (lane >= K8) return;
    const int beg = off[node], end = off[node + 1];
    const float di = dinv_in[node];
    const uint4* y8 = (const uint4*)y;
    const int c = lane;

    float acc[8] = {};
    for (int j = beg; j < end; j++) {
        const int s = csc[j];
        uint4 v = y8[(size_t)s * K8 + c];
        float2 f0 = unpack2h(v.x), f1 = unpack2h(v.y), f2 = unpack2h(v.z), f3 = unpack2h(v.w);
        acc[0] += f0.x; acc[1] += f0.y; acc[2] += f1.x; acc[3] += f1.y;
        acc[4] += f2.x; acc[5] += f2.y; acc[6] += f3.x; acc[7] += f3.y;
    }
    uint4 o;
    o.x = pack2h(acc[0] * di, acc[1] * di);
    o.y = pack2h(acc[2] * di, acc[3] * di);
    o.z = pack2h(acc[4] * di, acc[5] * di);
    o.w = pack2h(acc[6] * di, acc[7] * di);
    *reinterpret_cast<uint4*>(A + (size_t)node * sNext + c * 8) = o;
}

// ================= gather_post: agg = S t (fp16 rows, fp32 accum) =================
// act = leaky(dinv_in*agg + bias) * dinv_out -> fp16 A(next) or fp16 y (outY)
__global__ __launch_bounds__(256)
void gather_post(const __half* __restrict__ t, const int* __restrict__ off,
                 const int* __restrict__ csc, int N8, int cpn,
                 __half* __restrict__ A, int sNext,
                 const float* __restrict__ bias, const float* __restrict__ dinv_in,
                 const float* __restrict__ dinv_out, __half* __restrict__ outY, int sY) {
    const int gw = blockIdx.x * 8 + (threadIdx.x >> 5);
    const int lane = threadIdx.x & 31;
    const int node = gw / cpn, chunk = gw - node * cpn;
    if (node >= N_NODES) return;
    const int c = chunk * 32 + lane;
    if (c >= N8) return;

    const uint4* t8 = (const uint4*)t;
    const int beg = off[node], end = off[node + 1];
    float acc[8] = {};
    for (int j = beg; j < end; j++) {
        const int s = csc[j];
        uint4 v = t8[(size_t)s * N8 + c];
        float2 f0 = unpack2h(v.x), f1 = unpack2h(v.y), f2 = unpack2h(v.z), f3 = unpack2h(v.w);
        acc[0] += f0.x; acc[1] += f0.y; acc[2] += f1.x; acc[3] += f1.y;
        acc[4] += f2.x; acc[5] += f2.y; acc[6] += f3.x; acc[7] += f3.y;
    }
    const float di = dinv_in[node];
    const float dv = dinv_out[node];
    float v[8];
    #pragma unroll
    for (int i = 0; i < 8; i++) {
        float u = fmaf(acc[i], di, bias[c * 8 + i]);
        v[i] = ((u < 0.f) ? 0.01f * u : u) * dv;
    }
    uint4 o;
    o.x = pack2h(v[0], v[1]);
    o.y = pack2h(v[2], v[3]);
    o.z = pack2h(v[4], v[5]);
    o.w = pack2h(v[6], v[7]);
    if (outY)
        *reinterpret_cast<uint4*>(outY + (size_t)node * sY + c * 8) = o;
    else
        *reinterpret_cast<uint4*>(A + (size_t)node * sNext + c * 8) = o;
}

// ================= launch =================
extern "C" void kernel_launch(void* const* d_in, const int* in_sizes, int n_in,
                              void* d_out, int out_size) {
    const float* x = (const float*)d_in[0];
    const int* ei = (const int*)d_in[1];   // int32 (JAX x64 disabled)
    const float* W[5] = {(const float*)d_in[2], (const float*)d_in[4], (const float*)d_in[6],
                         (const float*)d_in[8], (const float*)d_in[10]};
    const float* B[5] = {(const float*)d_in[3], (const float*)d_in[5], (const float*)d_in[7],
                         (const float*)d_in[9], (const float*)d_in[11]};

    const int M = N_NODES;
    const int nE = N_EDGES;
    const int* src = ei;
    const int* dstp = ei + nE;

    float *doutP, *dinP;
    __half *tP, *yP, *A0, *A1, *WfP;
    int *idegP, *odegP, *offP, *curP, *cscP, *bsumP;
    cudaGetSymbolAddress((void**)&tP, g_t);
    cudaGetSymbolAddress((void**)&yP, g_y);
    cudaGetSymbolAddress((void**)&A0, g_A0);
    cudaGetSymbolAddress((void**)&A1, g_A1);
    cudaGetSymbolAddress((void**)&WfP, g_Wf);
    cudaGetSymbolAddress((void**)&doutP, g_dinv_out);
    cudaGetSymbolAddress((void**)&dinP, g_dinv_in);
    cudaGetSymbolAddress((void**)&idegP, g_ideg);
    cudaGetSymbolAddress((void**)&odegP, g_odeg);
    cudaGetSymbolAddress((void**)&offP, g_off);
    cudaGetSymbolAddress((void**)&curP, g_cur);
    cudaGetSymbolAddress((void**)&cscP, g_csc);
    cudaGetSymbolAddress((void**)&bsumP, g_bsum);

    cudaFuncSetAttribute(gemm_mma, cudaFuncAttributeMaxDynamicSharedMemorySize, SMEM_TOTAL_B);

    // degrees + parallel scan + CSC fill
    hist_kernel<<<(nE + 255) / 256, 256>>>(src, dstp, odegP, idegP, nE);
    blocksum_kernel<<<SCAN_NB, SCAN_BS>>>(idegP, bsumP);
    scanpart_kernel<<<1, 256>>>(bsumP, SCAN_NB);
    offsets_dinv_kernel<<<SCAN_NB, SCAN_BS>>>(idegP, odegP, bsumP, offP, curP, doutP, dinP);
    fill_kernel<<<(nE + 255) / 256, 256>>>(src, dstp, curP, cscP, nE);
    // layer-1 pre-aggregation (fp32 x, K=300 -> fp16 A0, stride 320)
    gather_pre<<<(M + 7) / 8, 256>>>(x, doutP, offP, cscP, 75, 80, A0, 320, dinP);
    // all weight planes
    prep_w_all<<<640, 256>>>(W[0], W[1], W[2], W[3], W[4], WfP);

    // Layer 1 GEMM (K=320, N=1024) epilogue -> fp16 A1
    {
        dim3 grid(1024 / 128, M_PAD / 128);
        gemm_mma<<<grid, 256, SMEM_TOTAL_B>>>(A0, WfP + WOFF0, nullptr,
                                              M, 1024, 320, 1, B[0], doutP, A1, 1024);
    }
    // Layer 2 (K=1024, N=512) -> fp16 t
    {
        dim3 grid(512 / 128, M_PAD / 128);
        gemm_mma<<<grid, 256, SMEM_TOTAL_B>>>(A1, WfP + WOFF1, nullptr,
                                              M, 512, 1024, 0, nullptr, nullptr, tP, 512);
    }
    gather_post<<<(M * 2 + 7) / 8, 256>>>(tP, offP, cscP, 64, 2, A0, 512,
                                          B[1], dinP, doutP, nullptr, 0);
    // Layer 3 (K=512, N=256) -> fp16 t
    {
        dim3 grid(256 / 128, M_PAD / 128);
        gemm_mma<<<grid, 256, SMEM_TOTAL_B>>>(A0, WfP + WOFF2, nullptr,
                                              M, 256, 512, 0, nullptr, nullptr, tP, 256);
    }
    gather_post<<<(M + 7) / 8, 256>>>(tP, offP, cscP, 32, 1, A1, 256,
                                      B[2], dinP, doutP, nullptr, 0);
    // Layer 4 (K=256, N=128) -> fp16 t -> fp16 y
    {
        dim3 grid(128 / 128, M_PAD / 128);
        gemm_mma<<<grid, 256, SMEM_TOTAL_B>>>(A1, WfP + WOFF3, nullptr,
                                              M, 128, 256, 0, nullptr, nullptr, tP, 128);
    }
    gather_post<<<(M + 7) / 8, 256>>>(tP, offP, cscP, 16, 1, nullptr, 0,
                                      B[3], dinP, doutP, yP, 128);
    // Layer 5 (aggregate-first, fp16 y, K=128, N=2048) -> d_out
    gather_pre_h<<<(M + 7) / 8, 256>>>(yP, offP, cscP, 16, A0, 128, dinP);
    {
        dim3 grid(2048 / 128, M_PAD / 128);
        gemm_mma<<<grid, 256, SMEM_TOTAL_B>>>(A0, WfP + WOFF4, (float*)d_out,
                                              M, 2048, 128, 2, B[4], nullptr, nullptr, 0);
    }
    // restore degree arrays for next replay
    cleanup_kernel<<<(M + 255) / 256, 256>>>(idegP, odegP);
}